// round 6
// baseline (speedup 1.0000x reference)
#include <cuda_runtime.h>
#include <math.h>

#define B_ 4
#define T_ 2048
#define C_ 1024
#define H_ 16
#define D_ 64

// Scratch (allocation-free rule: __device__ globals)
__device__ float g_qkv[(size_t)B_ * T_ * 3 * C_];   // [B,T,3C]
__device__ float g_y  [(size_t)B_ * T_ * C_];       // [B,T,C]

// ---------------------------------------------------------------------------
// OUT[m,n] = sum_k A[m,k] * W[n,k]   (A row-major [M,K], W row-major [N,K])
// BM=BN=128, BK=8, 256 threads, each computes 8x8.
// ---------------------------------------------------------------------------
__global__ __launch_bounds__(256) void gemm_tn(
    const float* __restrict__ A, const float* __restrict__ W,
    float* __restrict__ OUT, int M, int N, int K)
{
    const int BM = 128, BN = 128, BK = 8, TM = 8, TN = 8;
    __shared__ float As[BK][BM];
    __shared__ float Ws[BK][BN];

    const int tid  = threadIdx.x;           // 0..255
    const int tcol = tid % (BN / TN);       // 0..15
    const int trow = tid / (BN / TN);       // 0..15

    const float* Ablk = A + (size_t)blockIdx.y * BM * K;
    const float* Wblk = W + (size_t)blockIdx.x * BN * K;

    float acc[TM][TN];
#pragma unroll
    for (int i = 0; i < TM; i++)
#pragma unroll
        for (int j = 0; j < TN; j++) acc[i][j] = 0.f;

    const int lrow = tid / 2;            // 0..127
    const int lcol = (tid & 1) * 4;      // 0 or 4

    for (int k0 = 0; k0 < K; k0 += BK) {
        float4 a4 = *(const float4*)(Ablk + (size_t)lrow * K + k0 + lcol);
        float4 w4 = *(const float4*)(Wblk + (size_t)lrow * K + k0 + lcol);
        As[lcol + 0][lrow] = a4.x; As[lcol + 1][lrow] = a4.y;
        As[lcol + 2][lrow] = a4.z; As[lcol + 3][lrow] = a4.w;
        Ws[lcol + 0][lrow] = w4.x; Ws[lcol + 1][lrow] = w4.y;
        Ws[lcol + 2][lrow] = w4.z; Ws[lcol + 3][lrow] = w4.w;
        __syncthreads();

#pragma unroll
        for (int k = 0; k < BK; k++) {
            float ra[TM], rw[TN];
            const float4* a0 = (const float4*)&As[k][trow * TM];
            const float4* w0 = (const float4*)&Ws[k][tcol * TN];
            float4 t;
            t = a0[0]; ra[0]=t.x; ra[1]=t.y; ra[2]=t.z; ra[3]=t.w;
            t = a0[1]; ra[4]=t.x; ra[5]=t.y; ra[6]=t.z; ra[7]=t.w;
            t = w0[0]; rw[0]=t.x; rw[1]=t.y; rw[2]=t.z; rw[3]=t.w;
            t = w0[1]; rw[4]=t.x; rw[5]=t.y; rw[6]=t.z; rw[7]=t.w;
#pragma unroll
            for (int i = 0; i < TM; i++)
#pragma unroll
                for (int j = 0; j < TN; j++)
                    acc[i][j] += ra[i] * rw[j];
        }
        __syncthreads();
    }

    const int orow = blockIdx.y * BM + trow * TM;
    const int ocol = blockIdx.x * BN + tcol * TN;
#pragma unroll
    for (int i = 0; i < TM; i++) {
        float4* o = (float4*)(OUT + (size_t)(orow + i) * N + ocol);
        float4 v0 = make_float4(acc[i][0], acc[i][1], acc[i][2], acc[i][3]);
        float4 v1 = make_float4(acc[i][4], acc[i][5], acc[i][6], acc[i][7]);
        o[0] = v0; o[1] = v1;
    }
}

// ---------------------------------------------------------------------------
// Causal flash attention, fp32.
// Grid: (T/64, H, B). Block: 128 threads. Two threads per query row
// (each owns 32 of the 64 dims). K/V tiles of 64 keys staged in smem.
// Key loop is WARP-UNIFORM (always 64 iters/tile); causality applied by
// masking the score on the diagonal tile. This avoids the full-mask-shfl
// divergence deadlock.
// Writes y in [B,T,C] layout (y[b,t,h*64+d]).
// ---------------------------------------------------------------------------
__global__ __launch_bounds__(128) void attn_kernel(
    const float* __restrict__ qkv, float* __restrict__ y)
{
    const int qt  = blockIdx.x;    // query tile (64 queries)
    const int h   = blockIdx.y;
    const int b   = blockIdx.z;
    const int tid = threadIdx.x;
    const int qr   = tid >> 1;     // 0..63  query row within tile
    const int half = tid & 1;      // 0/1    which 32-dim half

    const int qi = qt * 64 + qr;
    const float scale = 0.125f;    // 1/sqrt(64)

    __shared__ float Ks[64][64];
    __shared__ float Vs[64][64];

    // Load q (scaled) into registers
    const float* qptr = qkv + ((size_t)(b * T_ + qi) * 3 * C_) + h * D_ + half * 32;
    float qreg[32];
#pragma unroll
    for (int j = 0; j < 8; j++) {
        float4 v = ((const float4*)qptr)[j];
        qreg[4*j+0] = v.x * scale; qreg[4*j+1] = v.y * scale;
        qreg[4*j+2] = v.z * scale; qreg[4*j+3] = v.w * scale;
    }

    float acc[32];
#pragma unroll
    for (int j = 0; j < 32; j++) acc[j] = 0.f;
    float m = -1e30f, l = 0.f;

    const size_t row_stride = (size_t)3 * C_;
    const float* kbase = qkv + ((size_t)b * T_) * row_stride + C_     + h * D_;
    const float* vbase = qkv + ((size_t)b * T_) * row_stride + 2 * C_ + h * D_;

    for (int kt = 0; kt <= qt; kt++) {
        // cooperative load of 64x64 K and V tiles (32 floats = 8 float4 each)
        const float* kt_base = kbase + (size_t)(kt * 64) * row_stride;
        const float* vt_base = vbase + (size_t)(kt * 64) * row_stride;
#pragma unroll
        for (int it = 0; it < 8; it++) {
            int lin = it * 512 + tid * 4;       // 0..4095
            int r = lin >> 6, c = lin & 63;
            *(float4*)&Ks[r][c] = *(const float4*)(kt_base + (size_t)r * row_stride + c);
            *(float4*)&Vs[r][c] = *(const float4*)(vt_base + (size_t)r * row_stride + c);
        }
        __syncthreads();

        const bool diag = (kt == qt);
        // Uniform trip count: every lane runs all 64 iterations.
        for (int kk = 0; kk < 64; kk++) {
            // partial dot over this thread's 32 dims
            float s = 0.f;
            const float4* kp = (const float4*)&Ks[kk][half * 32];
#pragma unroll
            for (int j = 0; j < 8; j++) {
                float4 v = kp[j];
                s += qreg[4*j+0] * v.x + qreg[4*j+1] * v.y
                   + qreg[4*j+2] * v.z + qreg[4*j+3] * v.w;
            }
            s += __shfl_xor_sync(0xffffffffu, s, 1);   // pair shares full dot

            // causal mask on the diagonal tile (kk=0 is always valid, so m
            // becomes finite on the first iteration — no inf-inf NaN path)
            if (diag && kk > qr) s = -1e30f;

            if (s > m) {
                float f = __expf(m - s);
                l *= f;
#pragma unroll
                for (int j = 0; j < 32; j++) acc[j] *= f;
                m = s;
            }
            float p = __expf(s - m);
            l += p;
            const float4* vp = (const float4*)&Vs[kk][half * 32];
#pragma unroll
            for (int j = 0; j < 8; j++) {
                float4 v = vp[j];
                acc[4*j+0] += p * v.x; acc[4*j+1] += p * v.y;
                acc[4*j+2] += p * v.z; acc[4*j+3] += p * v.w;
            }
        }
        __syncthreads();
    }

    const float inv = 1.f / l;
    float* yp = y + ((size_t)(b * T_ + qi) * C_) + h * D_ + half * 32;
#pragma unroll
    for (int j = 0; j < 8; j++) {
        float4 v = make_float4(acc[4*j+0]*inv, acc[4*j+1]*inv,
                               acc[4*j+2]*inv, acc[4*j+3]*inv);
        ((float4*)yp)[j] = v;
    }
}

// ---------------------------------------------------------------------------
extern "C" void kernel_launch(void* const* d_in, const int* in_sizes, int n_in,
                              void* d_out, int out_size)
{
    const float* x     = (const float*)d_in[0];   // [B,T,C]
    const float* w_qkv = (const float*)d_in[1];   // [3C,C]
    const float* w_out = (const float*)d_in[2];   // [C,C]
    float* out = (float*)d_out;                   // [B,T,C]

    float* qkv; cudaGetSymbolAddress((void**)&qkv, g_qkv);
    float* y;   cudaGetSymbolAddress((void**)&y,   g_y);

    const int M = B_ * T_;     // 8192

    // 1) qkv = x @ w_qkv^T : [8192,3072]
    {
        dim3 grid(3 * C_ / 128, M / 128);
        gemm_tn<<<grid, 256>>>(x, w_qkv, qkv, M, 3 * C_, C_);
    }
    // 2) causal attention -> y [B,T,C]
    {
        dim3 grid(T_ / 64, H_, B_);
        attn_kernel<<<grid, 128>>>(qkv, y);
    }
    // 3) out = y @ w_out^T : [8192,1024]
    {
        dim3 grid(C_ / 128, M / 128);
        gemm_tn<<<grid, 256>>>(y, w_out, out, M, C_, C_);
    }
}

// round 8
// speedup vs baseline: 1.3867x; 1.3867x over previous
#include <cuda_runtime.h>
#include <cuda_bf16.h>
#include <cstdint>
#include <math.h>

#define B_ 4
#define T_ 2048
#define C_ 1024
#define H_ 16
#define D_ 64

// ---------------------------------------------------------------------------
// Scratch (allocation-free rule: __device__ globals)
// ---------------------------------------------------------------------------
__device__ float g_qkv[(size_t)B_ * T_ * 3 * C_];            // [B,T,3C] fp32
__device__ float g_y  [(size_t)B_ * T_ * C_];                // [B,T,C]  fp32
__device__ __nv_bfloat16 g_xh[(size_t)B_ * T_ * C_];         // x hi/lo
__device__ __nv_bfloat16 g_xl[(size_t)B_ * T_ * C_];
__device__ __nv_bfloat16 g_yh[(size_t)B_ * T_ * C_];         // y hi/lo
__device__ __nv_bfloat16 g_yl[(size_t)B_ * T_ * C_];
__device__ __nv_bfloat16 g_wqh[(size_t)3 * C_ * C_];         // w_qkv hi/lo
__device__ __nv_bfloat16 g_wql[(size_t)3 * C_ * C_];
__device__ __nv_bfloat16 g_woh[(size_t)C_ * C_];             // w_out hi/lo
__device__ __nv_bfloat16 g_wol[(size_t)C_ * C_];

// ---------------------------------------------------------------------------
// Baseline-PTX tensor-core helpers (valid on compute_103: no tcgen05!)
// ---------------------------------------------------------------------------
__device__ __forceinline__ uint32_t smem_u32(const void* p) {
    uint32_t a;
    asm("{ .reg .u64 t; cvta.to.shared.u64 t, %1; cvt.u32.u64 %0, t; }" : "=r"(a) : "l"(p));
    return a;
}
__device__ __forceinline__ uint32_t swz128(uint32_t off) { return off ^ ((off >> 3) & 0x70); }

#define LDSM_X4(r0, r1, r2, r3, addr) \
    asm volatile("ldmatrix.sync.aligned.m8n8.x4.shared.b16 {%0,%1,%2,%3}, [%4];" \
        : "=r"(r0), "=r"(r1), "=r"(r2), "=r"(r3) : "r"(addr))

#define MMA16816(d, a, b) \
    asm volatile("mma.sync.aligned.m16n8k16.row.col.f32.bf16.bf16.f32 " \
        "{%0,%1,%2,%3}, {%4,%5,%6,%7}, {%8,%9}, {%0,%1,%2,%3};" \
        : "+f"((d)[0]), "+f"((d)[1]), "+f"((d)[2]), "+f"((d)[3]) \
        : "r"((a)[0]), "r"((a)[1]), "r"((a)[2]), "r"((a)[3]), "r"((b)[0]), "r"((b)[1]))

// ---------------------------------------------------------------------------
// hi/lo bf16 split:  x = hi + lo (+ O(2^-18 x))
// ---------------------------------------------------------------------------
__global__ __launch_bounds__(256) void split_kernel(
    const float* __restrict__ src, __nv_bfloat16* __restrict__ h,
    __nv_bfloat16* __restrict__ l, int n4)
{
    int i = blockIdx.x * 256 + threadIdx.x;
    if (i >= n4) return;
    float4 v = ((const float4*)src)[i];
    __nv_bfloat16 h0 = __float2bfloat16(v.x), h1 = __float2bfloat16(v.y);
    __nv_bfloat16 h2 = __float2bfloat16(v.z), h3 = __float2bfloat16(v.w);
    __nv_bfloat162* hp = (__nv_bfloat162*)(h + 4 * (size_t)i);
    hp[0] = __nv_bfloat162(h0, h1); hp[1] = __nv_bfloat162(h2, h3);
    __nv_bfloat16 l0 = __float2bfloat16(v.x - __bfloat162float(h0));
    __nv_bfloat16 l1 = __float2bfloat16(v.y - __bfloat162float(h1));
    __nv_bfloat16 l2 = __float2bfloat16(v.z - __bfloat162float(h2));
    __nv_bfloat16 l3 = __float2bfloat16(v.w - __bfloat162float(h3));
    __nv_bfloat162* lp = (__nv_bfloat162*)(l + 4 * (size_t)i);
    lp[0] = __nv_bfloat162(l0, l1); lp[1] = __nv_bfloat162(l2, l3);
}

// ---------------------------------------------------------------------------
// mma.sync bf16x3 GEMM:  OUT[m,n] = sum_k A[m,k] * B[n,k]
// D = Ah*Bh + Ah*Bl + Al*Bh  (fp32 accumulators in registers)
// CTA tile 128x128, BK=64, 256 threads = 8 warps in 4(M) x 2(N).
// Warp tile 32x64. Smem tiles: 128 rows x 64 bf16 (128B rows), Swizzle<3,4,3>.
// ---------------------------------------------------------------------------
#define SM_AH   0
#define SM_AL   16384
#define SM_BH   32768
#define SM_BL   49152
#define SM_TOTAL 65536

__global__ __launch_bounds__(256, 1) void gemm_bf16x3(
    const __nv_bfloat16* __restrict__ Ah, const __nv_bfloat16* __restrict__ Al,
    const __nv_bfloat16* __restrict__ Bh, const __nv_bfloat16* __restrict__ Bl,
    float* __restrict__ OUT, int N, int K)
{
    extern __shared__ char smem[];
    const uint32_t sb = smem_u32(smem);
    const int tid  = threadIdx.x;
    const int lane = tid & 31;
    const int warp = tid >> 5;
    const int wm   = warp >> 1;      // 0..3  (M direction, 32 rows each)
    const int wn   = warp & 1;       // 0..1  (N direction, 64 cols each)

    const size_t arow0 = (size_t)blockIdx.y * 128;
    const size_t brow0 = (size_t)blockIdx.x * 128;
    const __nv_bfloat16* pAh = Ah + arow0 * K;
    const __nv_bfloat16* pAl = Al + arow0 * K;
    const __nv_bfloat16* pBh = Bh + brow0 * K;
    const __nv_bfloat16* pBl = Bl + brow0 * K;

    float acc[2][8][4];
#pragma unroll
    for (int mt = 0; mt < 2; mt++)
#pragma unroll
        for (int nt = 0; nt < 8; nt++)
#pragma unroll
            for (int r = 0; r < 4; r++) acc[mt][nt][r] = 0.f;

    // ldmatrix per-lane source rows (addresses computed per step below)
    // A x4: lanes 0-15 -> rows (m0+lane), k0 ; lanes 16-31 -> rows, k0+8
    const int a_r  = lane & 15;
    const int a_k  = (lane >> 4) * 8;
    // B x4 (two n8 tiles): g=lane>>3: g0:(n0+rr,k0) g1:(n0+rr,k0+8) g2:(n0+8+rr,k0) g3:(n0+8+rr,k0+8)
    const int b_rr = lane & 7;
    const int b_g  = lane >> 3;
    const int b_n  = ((b_g >> 1) * 8) + b_rr;
    const int b_k  = (b_g & 1) * 8;

    const int nchunks = K >> 6;                 // K / 64
    for (int ch = 0; ch < nchunks; ch++) {
        const int k0 = ch << 6;
        // cooperative load: 4 tiles of 128 rows x 64 bf16 (rows = 128B, swizzled)
#pragma unroll
        for (int i = 0; i < 4; i++) {
            int ci = tid + i * 256;             // 0..1023 : (row, 16B chunk)
            int r = ci >> 3, c = ci & 7;
            uint32_t so = swz128((uint32_t)(r * 128 + c * 16));
            size_t go = (size_t)r * K + k0 + c * 8;
            *(uint4*)(smem + SM_AH + so) = *(const uint4*)(pAh + go);
            *(uint4*)(smem + SM_AL + so) = *(const uint4*)(pAl + go);
            *(uint4*)(smem + SM_BH + so) = *(const uint4*)(pBh + go);
            *(uint4*)(smem + SM_BL + so) = *(const uint4*)(pBl + go);
        }
        __syncthreads();

#pragma unroll
        for (int ks = 0; ks < 4; ks++) {        // 4 x k16 per chunk
            const int kk = ks * 16;
            // --- A fragments (2 m16 tiles, hi+lo) ---
            uint32_t fAh[2][4], fAl[2][4];
#pragma unroll
            for (int mt = 0; mt < 2; mt++) {
                uint32_t bo = swz128((uint32_t)((wm * 32 + mt * 16 + a_r) * 128 + (kk + a_k) * 2));
                LDSM_X4(fAh[mt][0], fAh[mt][1], fAh[mt][2], fAh[mt][3], sb + SM_AH + bo);
                LDSM_X4(fAl[mt][0], fAl[mt][1], fAl[mt][2], fAl[mt][3], sb + SM_AL + bo);
            }
            // --- B fragments (8 n8 tiles = 4 x4-loads, hi+lo) ---
            uint32_t fBh[8][2], fBl[8][2];
#pragma unroll
            for (int p = 0; p < 4; p++) {
                uint32_t bo = swz128((uint32_t)((wn * 64 + p * 16 + b_n) * 128 + (kk + b_k) * 2));
                uint32_t r0, r1, r2, r3;
                LDSM_X4(r0, r1, r2, r3, sb + SM_BH + bo);
                fBh[p*2][0] = r0; fBh[p*2][1] = r1; fBh[p*2+1][0] = r2; fBh[p*2+1][1] = r3;
                LDSM_X4(r0, r1, r2, r3, sb + SM_BL + bo);
                fBl[p*2][0] = r0; fBl[p*2][1] = r1; fBl[p*2+1][0] = r2; fBl[p*2+1][1] = r3;
            }
            // --- 48 MMAs, product-major so consecutive MMAs hit different acc ---
#pragma unroll
            for (int mt = 0; mt < 2; mt++)
#pragma unroll
                for (int nt = 0; nt < 8; nt++) MMA16816(acc[mt][nt], fAh[mt], fBh[nt]);
#pragma unroll
            for (int mt = 0; mt < 2; mt++)
#pragma unroll
                for (int nt = 0; nt < 8; nt++) MMA16816(acc[mt][nt], fAh[mt], fBl[nt]);
#pragma unroll
            for (int mt = 0; mt < 2; mt++)
#pragma unroll
                for (int nt = 0; nt < 8; nt++) MMA16816(acc[mt][nt], fAl[mt], fBh[nt]);
        }
        __syncthreads();
    }

    // epilogue: C fragment c0,c1 -> (row=lane/4, col=(lane%4)*2), c2,c3 -> row+8
    const int c_r = lane >> 2;
    const int c_c = (lane & 3) * 2;
#pragma unroll
    for (int mt = 0; mt < 2; mt++) {
        size_t row = arow0 + wm * 32 + mt * 16 + c_r;
        float* o0 = OUT + row * N       + brow0 + wn * 64 + c_c;
        float* o1 = OUT + (row + 8) * N + brow0 + wn * 64 + c_c;
#pragma unroll
        for (int nt = 0; nt < 8; nt++) {
            *(float2*)(o0 + nt * 8) = make_float2(acc[mt][nt][0], acc[mt][nt][1]);
            *(float2*)(o1 + nt * 8) = make_float2(acc[mt][nt][2], acc[mt][nt][3]);
        }
    }
}

// ---------------------------------------------------------------------------
// Causal flash attention, fp32 (unchanged, known correct).
// ---------------------------------------------------------------------------
__global__ __launch_bounds__(128) void attn_kernel(
    const float* __restrict__ qkv, float* __restrict__ y)
{
    const int qt  = blockIdx.x;
    const int h   = blockIdx.y;
    const int b   = blockIdx.z;
    const int tid = threadIdx.x;
    const int qr   = tid >> 1;
    const int half = tid & 1;

    const int qi = qt * 64 + qr;
    const float scale = 0.125f;

    __shared__ float Ks[64][64];
    __shared__ float Vs[64][64];

    const float* qptr = qkv + ((size_t)(b * T_ + qi) * 3 * C_) + h * D_ + half * 32;
    float qreg[32];
#pragma unroll
    for (int j = 0; j < 8; j++) {
        float4 v = ((const float4*)qptr)[j];
        qreg[4*j+0] = v.x * scale; qreg[4*j+1] = v.y * scale;
        qreg[4*j+2] = v.z * scale; qreg[4*j+3] = v.w * scale;
    }

    float acc[32];
#pragma unroll
    for (int j = 0; j < 32; j++) acc[j] = 0.f;
    float m = -1e30f, l = 0.f;

    const size_t row_stride = (size_t)3 * C_;
    const float* kbase = qkv + ((size_t)b * T_) * row_stride + C_     + h * D_;
    const float* vbase = qkv + ((size_t)b * T_) * row_stride + 2 * C_ + h * D_;

    for (int kt = 0; kt <= qt; kt++) {
        const float* kt_base = kbase + (size_t)(kt * 64) * row_stride;
        const float* vt_base = vbase + (size_t)(kt * 64) * row_stride;
#pragma unroll
        for (int it = 0; it < 8; it++) {
            int lin = it * 512 + tid * 4;
            int r = lin >> 6, c = lin & 63;
            *(float4*)&Ks[r][c] = *(const float4*)(kt_base + (size_t)r * row_stride + c);
            *(float4*)&Vs[r][c] = *(const float4*)(vt_base + (size_t)r * row_stride + c);
        }
        __syncthreads();

        const bool diag = (kt == qt);
        for (int kk = 0; kk < 64; kk++) {
            float s = 0.f;
            const float4* kp = (const float4*)&Ks[kk][half * 32];
#pragma unroll
            for (int j = 0; j < 8; j++) {
                float4 v = kp[j];
                s += qreg[4*j+0] * v.x + qreg[4*j+1] * v.y
                   + qreg[4*j+2] * v.z + qreg[4*j+3] * v.w;
            }
            s += __shfl_xor_sync(0xffffffffu, s, 1);

            if (diag && kk > qr) s = -1e30f;

            if (s > m) {
                float f = __expf(m - s);
                l *= f;
#pragma unroll
                for (int j = 0; j < 32; j++) acc[j] *= f;
                m = s;
            }
            float p = __expf(s - m);
            l += p;
            const float4* vp = (const float4*)&Vs[kk][half * 32];
#pragma unroll
            for (int j = 0; j < 8; j++) {
                float4 v = vp[j];
                acc[4*j+0] += p * v.x; acc[4*j+1] += p * v.y;
                acc[4*j+2] += p * v.z; acc[4*j+3] += p * v.w;
            }
        }
        __syncthreads();
    }

    const float inv = 1.f / l;
    float* yp = y + ((size_t)(b * T_ + qi) * C_) + h * D_ + half * 32;
#pragma unroll
    for (int j = 0; j < 8; j++) {
        float4 v = make_float4(acc[4*j+0]*inv, acc[4*j+1]*inv,
                               acc[4*j+2]*inv, acc[4*j+3]*inv);
        ((float4*)yp)[j] = v;
    }
}

// ---------------------------------------------------------------------------
extern "C" void kernel_launch(void* const* d_in, const int* in_sizes, int n_in,
                              void* d_out, int out_size)
{
    const float* x     = (const float*)d_in[0];   // [B,T,C]
    const float* w_qkv = (const float*)d_in[1];   // [3C,C]
    const float* w_out = (const float*)d_in[2];   // [C,C]
    float* out = (float*)d_out;                   // [B,T,C]

    float *qkv, *y;
    cudaGetSymbolAddress((void**)&qkv, g_qkv);
    cudaGetSymbolAddress((void**)&y,   g_y);
    __nv_bfloat16 *xh, *xl, *yh, *yl, *wqh, *wql, *woh, *wol;
    cudaGetSymbolAddress((void**)&xh,  g_xh);  cudaGetSymbolAddress((void**)&xl,  g_xl);
    cudaGetSymbolAddress((void**)&yh,  g_yh);  cudaGetSymbolAddress((void**)&yl,  g_yl);
    cudaGetSymbolAddress((void**)&wqh, g_wqh); cudaGetSymbolAddress((void**)&wql, g_wql);
    cudaGetSymbolAddress((void**)&woh, g_woh); cudaGetSymbolAddress((void**)&wol, g_wol);

    cudaFuncSetAttribute(gemm_bf16x3, cudaFuncAttributeMaxDynamicSharedMemorySize, SM_TOTAL);

    const int M = B_ * T_;                  // 8192
    const int n_x  = M * C_;
    const int n_wq = 3 * C_ * C_;
    const int n_wo = C_ * C_;

    // hi/lo splits
    split_kernel<<<(n_x / 4 + 255) / 256, 256>>>(x, xh, xl, n_x / 4);
    split_kernel<<<(n_wq / 4 + 255) / 256, 256>>>(w_qkv, wqh, wql, n_wq / 4);
    split_kernel<<<(n_wo / 4 + 255) / 256, 256>>>(w_out, woh, wol, n_wo / 4);

    // 1) qkv = x @ w_qkv^T : [8192, 3072]  (tensor cores via mma.sync)
    {
        dim3 grid(3 * C_ / 128, M / 128);
        gemm_bf16x3<<<grid, 256, SM_TOTAL>>>(xh, xl, wqh, wql, qkv, 3 * C_, C_);
    }
    // 2) causal attention -> y [B,T,C]
    {
        dim3 grid(T_ / 64, H_, B_);
        attn_kernel<<<grid, 128>>>(qkv, y);
    }
    // 3) out = y @ w_out^T : [8192, 1024]  (tensor cores via mma.sync)
    split_kernel<<<(n_x / 4 + 255) / 256, 256>>>(y, yh, yl, n_x / 4);
    {
        dim3 grid(C_ / 128, M / 128);
        gemm_bf16x3<<<grid, 256, SM_TOTAL>>>(yh, yl, woh, wol, out, C_, C_);
    }
}

// round 9
// speedup vs baseline: 3.4034x; 2.4544x over previous
#include <cuda_runtime.h>
#include <cuda_bf16.h>
#include <cstdint>
#include <math.h>

#define B_ 4
#define T_ 2048
#define C_ 1024
#define H_ 16
#define D_ 64

// ---------------------------------------------------------------------------
// Scratch (allocation-free rule: __device__ globals)
// ---------------------------------------------------------------------------
__device__ float g_qkv[(size_t)B_ * T_ * 3 * C_];            // [B,T,3C] fp32
__device__ __nv_bfloat16 g_xh[(size_t)B_ * T_ * C_];         // x hi/lo
__device__ __nv_bfloat16 g_xl[(size_t)B_ * T_ * C_];
__device__ __nv_bfloat16 g_yh[(size_t)B_ * T_ * C_];         // y hi/lo (written by attn)
__device__ __nv_bfloat16 g_yl[(size_t)B_ * T_ * C_];
__device__ __nv_bfloat16 g_wqh[(size_t)3 * C_ * C_];         // w_qkv hi/lo
__device__ __nv_bfloat16 g_wql[(size_t)3 * C_ * C_];
__device__ __nv_bfloat16 g_woh[(size_t)C_ * C_];             // w_out hi/lo
__device__ __nv_bfloat16 g_wol[(size_t)C_ * C_];

// ---------------------------------------------------------------------------
// Baseline-PTX tensor-core helpers (valid on compute_103: no tcgen05!)
// ---------------------------------------------------------------------------
__device__ __forceinline__ uint32_t smem_u32(const void* p) {
    uint32_t a;
    asm("{ .reg .u64 t; cvta.to.shared.u64 t, %1; cvt.u32.u64 %0, t; }" : "=r"(a) : "l"(p));
    return a;
}
__device__ __forceinline__ uint32_t swz128(uint32_t off) { return off ^ ((off >> 3) & 0x70); }

#define LDSM_X4(r0, r1, r2, r3, addr) \
    asm volatile("ldmatrix.sync.aligned.m8n8.x4.shared.b16 {%0,%1,%2,%3}, [%4];" \
        : "=r"(r0), "=r"(r1), "=r"(r2), "=r"(r3) : "r"(addr))

#define MMA16816(d, a, b) \
    asm volatile("mma.sync.aligned.m16n8k16.row.col.f32.bf16.bf16.f32 " \
        "{%0,%1,%2,%3}, {%4,%5,%6,%7}, {%8,%9}, {%0,%1,%2,%3};" \
        : "+f"((d)[0]), "+f"((d)[1]), "+f"((d)[2]), "+f"((d)[3]) \
        : "r"((a)[0]), "r"((a)[1]), "r"((a)[2]), "r"((a)[3]), "r"((b)[0]), "r"((b)[1]))

// pack two fp32 -> bf16x2 (lo = first arg, hi = second arg)
__device__ __forceinline__ uint32_t pack_bf16x2(float lo, float hi) {
    uint32_t r;
    asm("cvt.rn.bf16x2.f32 %0, %1, %2;" : "=r"(r) : "f"(hi), "f"(lo));
    return r;
}
__device__ __forceinline__ float bf16lo_f(uint32_t p) { return __uint_as_float(p << 16); }
__device__ __forceinline__ float bf16hi_f(uint32_t p) { return __uint_as_float(p & 0xffff0000u); }

// ---------------------------------------------------------------------------
// hi/lo bf16 split:  x = hi + lo (+ O(2^-18 x))
// ---------------------------------------------------------------------------
__global__ __launch_bounds__(256) void split_kernel(
    const float* __restrict__ src, __nv_bfloat16* __restrict__ h,
    __nv_bfloat16* __restrict__ l, int n4)
{
    int i = blockIdx.x * 256 + threadIdx.x;
    if (i >= n4) return;
    float4 v = ((const float4*)src)[i];
    __nv_bfloat16 h0 = __float2bfloat16(v.x), h1 = __float2bfloat16(v.y);
    __nv_bfloat16 h2 = __float2bfloat16(v.z), h3 = __float2bfloat16(v.w);
    __nv_bfloat162* hp = (__nv_bfloat162*)(h + 4 * (size_t)i);
    hp[0] = __nv_bfloat162(h0, h1); hp[1] = __nv_bfloat162(h2, h3);
    __nv_bfloat16 l0 = __float2bfloat16(v.x - __bfloat162float(h0));
    __nv_bfloat16 l1 = __float2bfloat16(v.y - __bfloat162float(h1));
    __nv_bfloat16 l2 = __float2bfloat16(v.z - __bfloat162float(h2));
    __nv_bfloat16 l3 = __float2bfloat16(v.w - __bfloat162float(h3));
    __nv_bfloat162* lp = (__nv_bfloat162*)(l + 4 * (size_t)i);
    lp[0] = __nv_bfloat162(l0, l1); lp[1] = __nv_bfloat162(l2, l3);
}

// ---------------------------------------------------------------------------
// mma.sync bf16x3 GEMM (unchanged from R8, validated):
// OUT[m,n] = sum_k A[m,k]*B[n,k];  D = Ah*Bh + Ah*Bl + Al*Bh
// ---------------------------------------------------------------------------
#define SM_AH   0
#define SM_AL   16384
#define SM_BH   32768
#define SM_BL   49152
#define SM_TOTAL 65536

__global__ __launch_bounds__(256, 1) void gemm_bf16x3(
    const __nv_bfloat16* __restrict__ Ah, const __nv_bfloat16* __restrict__ Al,
    const __nv_bfloat16* __restrict__ Bh, const __nv_bfloat16* __restrict__ Bl,
    float* __restrict__ OUT, int N, int K)
{
    extern __shared__ char smem[];
    const uint32_t sb = smem_u32(smem);
    const int tid  = threadIdx.x;
    const int lane = tid & 31;
    const int warp = tid >> 5;
    const int wm   = warp >> 1;
    const int wn   = warp & 1;

    const size_t arow0 = (size_t)blockIdx.y * 128;
    const size_t brow0 = (size_t)blockIdx.x * 128;
    const __nv_bfloat16* pAh = Ah + arow0 * K;
    const __nv_bfloat16* pAl = Al + arow0 * K;
    const __nv_bfloat16* pBh = Bh + brow0 * K;
    const __nv_bfloat16* pBl = Bl + brow0 * K;

    float acc[2][8][4];
#pragma unroll
    for (int mt = 0; mt < 2; mt++)
#pragma unroll
        for (int nt = 0; nt < 8; nt++)
#pragma unroll
            for (int r = 0; r < 4; r++) acc[mt][nt][r] = 0.f;

    const int a_r  = lane & 15;
    const int a_k  = (lane >> 4) * 8;
    const int b_rr = lane & 7;
    const int b_g  = lane >> 3;
    const int b_n  = ((b_g >> 1) * 8) + b_rr;
    const int b_k  = (b_g & 1) * 8;

    const int nchunks = K >> 6;
    for (int ch = 0; ch < nchunks; ch++) {
        const int k0 = ch << 6;
#pragma unroll
        for (int i = 0; i < 4; i++) {
            int ci = tid + i * 256;
            int r = ci >> 3, c = ci & 7;
            uint32_t so = swz128((uint32_t)(r * 128 + c * 16));
            size_t go = (size_t)r * K + k0 + c * 8;
            *(uint4*)(smem + SM_AH + so) = *(const uint4*)(pAh + go);
            *(uint4*)(smem + SM_AL + so) = *(const uint4*)(pAl + go);
            *(uint4*)(smem + SM_BH + so) = *(const uint4*)(pBh + go);
            *(uint4*)(smem + SM_BL + so) = *(const uint4*)(pBl + go);
        }
        __syncthreads();

#pragma unroll
        for (int ks = 0; ks < 4; ks++) {
            const int kk = ks * 16;
            uint32_t fAh[2][4], fAl[2][4];
#pragma unroll
            for (int mt = 0; mt < 2; mt++) {
                uint32_t bo = swz128((uint32_t)((wm * 32 + mt * 16 + a_r) * 128 + (kk + a_k) * 2));
                LDSM_X4(fAh[mt][0], fAh[mt][1], fAh[mt][2], fAh[mt][3], sb + SM_AH + bo);
                LDSM_X4(fAl[mt][0], fAl[mt][1], fAl[mt][2], fAl[mt][3], sb + SM_AL + bo);
            }
            uint32_t fBh[8][2], fBl[8][2];
#pragma unroll
            for (int p = 0; p < 4; p++) {
                uint32_t bo = swz128((uint32_t)((wn * 64 + p * 16 + b_n) * 128 + (kk + b_k) * 2));
                uint32_t r0, r1, r2, r3;
                LDSM_X4(r0, r1, r2, r3, sb + SM_BH + bo);
                fBh[p*2][0] = r0; fBh[p*2][1] = r1; fBh[p*2+1][0] = r2; fBh[p*2+1][1] = r3;
                LDSM_X4(r0, r1, r2, r3, sb + SM_BL + bo);
                fBl[p*2][0] = r0; fBl[p*2][1] = r1; fBl[p*2+1][0] = r2; fBl[p*2+1][1] = r3;
            }
#pragma unroll
            for (int mt = 0; mt < 2; mt++)
#pragma unroll
                for (int nt = 0; nt < 8; nt++) MMA16816(acc[mt][nt], fAh[mt], fBh[nt]);
#pragma unroll
            for (int mt = 0; mt < 2; mt++)
#pragma unroll
                for (int nt = 0; nt < 8; nt++) MMA16816(acc[mt][nt], fAh[mt], fBl[nt]);
#pragma unroll
            for (int mt = 0; mt < 2; mt++)
#pragma unroll
                for (int nt = 0; nt < 8; nt++) MMA16816(acc[mt][nt], fAl[mt], fBh[nt]);
        }
        __syncthreads();
    }

    const int c_r = lane >> 2;
    const int c_c = (lane & 3) * 2;
#pragma unroll
    for (int mt = 0; mt < 2; mt++) {
        size_t row = arow0 + wm * 32 + mt * 16 + c_r;
        float* o0 = OUT + row * N       + brow0 + wn * 64 + c_c;
        float* o1 = OUT + (row + 8) * N + brow0 + wn * 64 + c_c;
#pragma unroll
        for (int nt = 0; nt < 8; nt++) {
            *(float2*)(o0 + nt * 8) = make_float2(acc[mt][nt][0], acc[mt][nt][1]);
            *(float2*)(o1 + nt * 8) = make_float2(acc[mt][nt][2], acc[mt][nt][3]);
        }
    }
}

// ---------------------------------------------------------------------------
// Tensor-core causal flash attention (FA2 layout), bf16 hi/lo everywhere.
// CTA = 128 queries of one (b,h). 8 warps x 16 query rows. Key blocks of 64.
// K smem [key][d] (B-frag like GEMM, proven); V transposed to [d][key]
// (same B-frag pattern, n=d, k=key). S C-frags reused as PV A-frags.
// Writes yh/yl bf16 hi/lo directly (skips fp32 y + split pass).
// ---------------------------------------------------------------------------
#define AT_QH  0
#define AT_QL  16384
#define AT_KH  32768
#define AT_KL  40960
#define AT_VTH 49152
#define AT_VTL 57344
#define AT_TOTAL 65536

__global__ __launch_bounds__(256, 1) void attn_mma(
    const float* __restrict__ qkv,
    __nv_bfloat16* __restrict__ yh, __nv_bfloat16* __restrict__ yl)
{
    extern __shared__ char smem[];
    const uint32_t sb = smem_u32(smem);
    const int qt   = blockIdx.x;    // 128-query tile
    const int h    = blockIdx.y;
    const int b    = blockIdx.z;
    const int tid  = threadIdx.x;
    const int lane = tid & 31;
    const int warp = tid >> 5;

    const size_t rs = (size_t)3 * C_;             // qkv row stride
    const float* Qg = qkv + ((size_t)(b * T_ + qt * 128)) * rs + h * D_;
    const float* Kg = qkv + ((size_t)b * T_) * rs + C_     + h * D_;
    const float* Vg = qkv + ((size_t)b * T_) * rs + 2 * C_ + h * D_;

    // ---- load + convert Q (scale folded into hi/lo split) ----
#pragma unroll
    for (int i = 0; i < 8; i++) {
        int lin = i * 256 + tid;                  // 0..2047
        int r = lin >> 4, c4 = (lin & 15) * 4;
        float4 v = *(const float4*)(Qg + (size_t)r * rs + c4);
        v.x *= 0.125f; v.y *= 0.125f; v.z *= 0.125f; v.w *= 0.125f;
        uint32_t h01 = pack_bf16x2(v.x, v.y), h23 = pack_bf16x2(v.z, v.w);
        uint32_t l01 = pack_bf16x2(v.x - bf16lo_f(h01), v.y - bf16hi_f(h01));
        uint32_t l23 = pack_bf16x2(v.z - bf16lo_f(h23), v.w - bf16hi_f(h23));
        uint32_t so = swz128((uint32_t)(r * 128 + (c4 >> 3) * 16)) + (c4 & 7) * 2;
        *(uint32_t*)(smem + AT_QH + so)     = h01;
        *(uint32_t*)(smem + AT_QH + so + 4) = h23;
        *(uint32_t*)(smem + AT_QL + so)     = l01;
        *(uint32_t*)(smem + AT_QL + so + 4) = l23;
    }
    __syncthreads();

    // ---- Q fragments (resident) ----
    const int a_r = lane & 15, a_k = (lane >> 4) * 8;
    uint32_t fQh[4][4], fQl[4][4];
#pragma unroll
    for (int ks = 0; ks < 4; ks++) {
        uint32_t bo = swz128((uint32_t)((warp * 16 + a_r) * 128 + (ks * 16 + a_k) * 2));
        LDSM_X4(fQh[ks][0], fQh[ks][1], fQh[ks][2], fQh[ks][3], sb + AT_QH + bo);
        LDSM_X4(fQl[ks][0], fQl[ks][1], fQl[ks][2], fQl[ks][3], sb + AT_QL + bo);
    }

    float oacc[8][4];
#pragma unroll
    for (int j = 0; j < 8; j++)
#pragma unroll
        for (int r = 0; r < 4; r++) oacc[j][r] = 0.f;
    float mrow[2] = {-1e30f, -1e30f};
    float lrow[2] = {0.f, 0.f};

    const int b_rr = lane & 7, b_g = lane >> 3;
    const int b_row = (b_g >> 1) * 8 + b_rr;      // row within ntile pair
    const int b_k   = (b_g & 1) * 8;

    const int qg0 = qt * 128 + warp * 16 + (lane >> 2);   // this lane's row r
    const int nb  = 2 * (qt + 1);

    for (int kb = 0; kb < nb; kb++) {
        // ---- load K (hi/lo) and V (hi/lo, transposed) into smem ----
        const float* Kt = Kg + (size_t)(kb * 64) * rs;
        const float* Vt = Vg + (size_t)(kb * 64) * rs;
#pragma unroll
        for (int i = 0; i < 4; i++) {
            int lin = i * 256 + tid;              // 0..1023
            int r = lin >> 4, c4 = (lin & 15) * 4;
            float4 v = *(const float4*)(Kt + (size_t)r * rs + c4);
            uint32_t h01 = pack_bf16x2(v.x, v.y), h23 = pack_bf16x2(v.z, v.w);
            uint32_t l01 = pack_bf16x2(v.x - bf16lo_f(h01), v.y - bf16hi_f(h01));
            uint32_t l23 = pack_bf16x2(v.z - bf16lo_f(h23), v.w - bf16hi_f(h23));
            uint32_t so = swz128((uint32_t)(r * 128 + (c4 >> 3) * 16)) + (c4 & 7) * 2;
            *(uint32_t*)(smem + AT_KH + so)     = h01;
            *(uint32_t*)(smem + AT_KH + so + 4) = h23;
            *(uint32_t*)(smem + AT_KL + so)     = l01;
            *(uint32_t*)(smem + AT_KL + so + 4) = l23;

            // V transpose: element (k=r, d=c4+e) -> Vt[d][k]
            float4 w = *(const float4*)(Vt + (size_t)r * rs + c4);
            float vv[4] = {w.x, w.y, w.z, w.w};
#pragma unroll
            for (int e = 0; e < 4; e++) {
                int d = c4 + e;
                __nv_bfloat16 hv = __float2bfloat16(vv[e]);
                __nv_bfloat16 lv = __float2bfloat16(vv[e] - __bfloat162float(hv));
                uint32_t off = swz128((uint32_t)(d * 128 + (r >> 3) * 16)) + (r & 7) * 2;
                *(__nv_bfloat16*)(smem + AT_VTH + off) = hv;
                *(__nv_bfloat16*)(smem + AT_VTL + off) = lv;
            }
        }
        __syncthreads();

        // ---- S = Q K^T (bf16x3) ----
        float sacc[8][4];
#pragma unroll
        for (int j = 0; j < 8; j++)
#pragma unroll
            for (int r = 0; r < 4; r++) sacc[j][r] = 0.f;
#pragma unroll
        for (int ks = 0; ks < 4; ks++) {
#pragma unroll
            for (int p = 0; p < 4; p++) {
                uint32_t bo = swz128((uint32_t)((p * 16 + b_row) * 128 + (ks * 16 + b_k) * 2));
                uint32_t bh[2][2], bl[2][2], r0, r1, r2, r3;
                LDSM_X4(r0, r1, r2, r3, sb + AT_KH + bo);
                bh[0][0] = r0; bh[0][1] = r1; bh[1][0] = r2; bh[1][1] = r3;
                LDSM_X4(r0, r1, r2, r3, sb + AT_KL + bo);
                bl[0][0] = r0; bl[0][1] = r1; bl[1][0] = r2; bl[1][1] = r3;
                MMA16816(sacc[2*p],   fQh[ks], bh[0]);
                MMA16816(sacc[2*p+1], fQh[ks], bh[1]);
                MMA16816(sacc[2*p],   fQh[ks], bl[0]);
                MMA16816(sacc[2*p+1], fQh[ks], bl[1]);
                MMA16816(sacc[2*p],   fQl[ks], bh[0]);
                MMA16816(sacc[2*p+1], fQl[ks], bh[1]);
            }
        }

        // ---- causal mask (only blocks touching the diagonal) ----
        if (kb >= 2 * qt) {
            const int kbase = kb * 64 + (lane & 3) * 2;
#pragma unroll
            for (int j = 0; j < 8; j++) {
#pragma unroll
                for (int cc = 0; cc < 2; cc++) {
                    int kg = kbase + j * 8 + cc;
                    if (kg > qg0)     sacc[j][cc]     = -1e30f;
                    if (kg > qg0 + 8) sacc[j][2 + cc] = -1e30f;
                }
            }
        }

        // ---- online softmax on fragments ----
        float m0 = mrow[0], m1 = mrow[1];
#pragma unroll
        for (int j = 0; j < 8; j++) {
            m0 = fmaxf(m0, fmaxf(sacc[j][0], sacc[j][1]));
            m1 = fmaxf(m1, fmaxf(sacc[j][2], sacc[j][3]));
        }
        m0 = fmaxf(m0, __shfl_xor_sync(0xffffffffu, m0, 1));
        m0 = fmaxf(m0, __shfl_xor_sync(0xffffffffu, m0, 2));
        m1 = fmaxf(m1, __shfl_xor_sync(0xffffffffu, m1, 1));
        m1 = fmaxf(m1, __shfl_xor_sync(0xffffffffu, m1, 2));
        const float f0 = __expf(mrow[0] - m0), f1 = __expf(mrow[1] - m1);
        mrow[0] = m0; mrow[1] = m1;
        lrow[0] *= f0; lrow[1] *= f1;
#pragma unroll
        for (int j = 0; j < 8; j++) {
            oacc[j][0] *= f0; oacc[j][1] *= f0;
            oacc[j][2] *= f1; oacc[j][3] *= f1;
        }

        // p = exp(s - m), packed into PV A-frags (hi/lo)
        uint32_t ah[4][4], al[4][4];
#pragma unroll
        for (int j = 0; j < 8; j++) {
            float p0 = __expf(sacc[j][0] - m0);
            float p1 = __expf(sacc[j][1] - m0);
            float p2 = __expf(sacc[j][2] - m1);
            float p3 = __expf(sacc[j][3] - m1);
            lrow[0] += p0 + p1;
            lrow[1] += p2 + p3;
            uint32_t ph01 = pack_bf16x2(p0, p1);
            uint32_t ph23 = pack_bf16x2(p2, p3);
            uint32_t pl01 = pack_bf16x2(p0 - bf16lo_f(ph01), p1 - bf16hi_f(ph01));
            uint32_t pl23 = pack_bf16x2(p2 - bf16lo_f(ph23), p3 - bf16hi_f(ph23));
            const int ks = j >> 1, sl = (j & 1) * 2;
            ah[ks][sl]     = ph01;  ah[ks][sl + 1] = ph23;
            al[ks][sl]     = pl01;  al[ks][sl + 1] = pl23;
        }

        // ---- O += P V (bf16x3) ----
#pragma unroll
        for (int ks = 0; ks < 4; ks++) {
#pragma unroll
            for (int p = 0; p < 4; p++) {
                uint32_t bo = swz128((uint32_t)((p * 16 + b_row) * 128 + (ks * 16 + b_k) * 2));
                uint32_t vh[2][2], vl[2][2], r0, r1, r2, r3;
                LDSM_X4(r0, r1, r2, r3, sb + AT_VTH + bo);
                vh[0][0] = r0; vh[0][1] = r1; vh[1][0] = r2; vh[1][1] = r3;
                LDSM_X4(r0, r1, r2, r3, sb + AT_VTL + bo);
                vl[0][0] = r0; vl[0][1] = r1; vl[1][0] = r2; vl[1][1] = r3;
                MMA16816(oacc[2*p],   ah[ks], vh[0]);
                MMA16816(oacc[2*p+1], ah[ks], vh[1]);
                MMA16816(oacc[2*p],   ah[ks], vl[0]);
                MMA16816(oacc[2*p+1], ah[ks], vl[1]);
                MMA16816(oacc[2*p],   al[ks], vh[0]);
                MMA16816(oacc[2*p+1], al[ks], vh[1]);
            }
        }
        __syncthreads();     // before smem K/V reuse
    }

    // ---- finalize: row-sum reduce, normalize, write yh/yl ----
    lrow[0] += __shfl_xor_sync(0xffffffffu, lrow[0], 1);
    lrow[0] += __shfl_xor_sync(0xffffffffu, lrow[0], 2);
    lrow[1] += __shfl_xor_sync(0xffffffffu, lrow[1], 1);
    lrow[1] += __shfl_xor_sync(0xffffffffu, lrow[1], 2);
    const float inv0 = 1.f / lrow[0], inv1 = 1.f / lrow[1];

    const int t0 = qt * 128 + warp * 16 + (lane >> 2);
    const size_t base0 = ((size_t)(b * T_ + t0)) * C_ + h * D_ + (lane & 3) * 2;
    const size_t base1 = base0 + 8 * (size_t)C_;
#pragma unroll
    for (int j = 0; j < 8; j++) {
        float y0 = oacc[j][0] * inv0, y1 = oacc[j][1] * inv0;
        float y2 = oacc[j][2] * inv1, y3 = oacc[j][3] * inv1;
        uint32_t h01 = pack_bf16x2(y0, y1);
        uint32_t l01 = pack_bf16x2(y0 - bf16lo_f(h01), y1 - bf16hi_f(h01));
        uint32_t h23 = pack_bf16x2(y2, y3);
        uint32_t l23 = pack_bf16x2(y2 - bf16lo_f(h23), y3 - bf16hi_f(h23));
        *(uint32_t*)(yh + base0 + j * 8) = h01;
        *(uint32_t*)(yl + base0 + j * 8) = l01;
        *(uint32_t*)(yh + base1 + j * 8) = h23;
        *(uint32_t*)(yl + base1 + j * 8) = l23;
    }
}

// ---------------------------------------------------------------------------
extern "C" void kernel_launch(void* const* d_in, const int* in_sizes, int n_in,
                              void* d_out, int out_size)
{
    const float* x     = (const float*)d_in[0];   // [B,T,C]
    const float* w_qkv = (const float*)d_in[1];   // [3C,C]
    const float* w_out = (const float*)d_in[2];   // [C,C]
    float* out = (float*)d_out;                   // [B,T,C]

    float* qkv;
    cudaGetSymbolAddress((void**)&qkv, g_qkv);
    __nv_bfloat16 *xh, *xl, *yh, *yl, *wqh, *wql, *woh, *wol;
    cudaGetSymbolAddress((void**)&xh,  g_xh);  cudaGetSymbolAddress((void**)&xl,  g_xl);
    cudaGetSymbolAddress((void**)&yh,  g_yh);  cudaGetSymbolAddress((void**)&yl,  g_yl);
    cudaGetSymbolAddress((void**)&wqh, g_wqh); cudaGetSymbolAddress((void**)&wql, g_wql);
    cudaGetSymbolAddress((void**)&woh, g_woh); cudaGetSymbolAddress((void**)&wol, g_wol);

    cudaFuncSetAttribute(gemm_bf16x3, cudaFuncAttributeMaxDynamicSharedMemorySize, SM_TOTAL);
    cudaFuncSetAttribute(attn_mma,    cudaFuncAttributeMaxDynamicSharedMemorySize, AT_TOTAL);

    const int M = B_ * T_;                  // 8192
    const int n_x  = M * C_;
    const int n_wq = 3 * C_ * C_;
    const int n_wo = C_ * C_;

    // hi/lo splits of inputs
    split_kernel<<<(n_x / 4 + 255) / 256, 256>>>(x, xh, xl, n_x / 4);
    split_kernel<<<(n_wq / 4 + 255) / 256, 256>>>(w_qkv, wqh, wql, n_wq / 4);
    split_kernel<<<(n_wo / 4 + 255) / 256, 256>>>(w_out, woh, wol, n_wo / 4);

    // 1) qkv = x @ w_qkv^T : [8192, 3072]
    {
        dim3 grid(3 * C_ / 128, M / 128);
        gemm_bf16x3<<<grid, 256, SM_TOTAL>>>(xh, xl, wqh, wql, qkv, 3 * C_, C_);
    }
    // 2) causal attention -> yh/yl bf16 hi/lo directly
    {
        dim3 grid(T_ / 128, H_, B_);
        attn_mma<<<grid, 256, AT_TOTAL>>>(qkv, yh, yl);
    }
    // 3) out = y @ w_out^T : [8192, 1024]
    {
        dim3 grid(C_ / 128, M / 128);
        gemm_bf16x3<<<grid, 256, SM_TOTAL>>>(yh, yl, woh, wol, out, C_, C_);
    }
}

// round 10
// speedup vs baseline: 4.6938x; 1.3792x over previous
#include <cuda_runtime.h>
#include <cuda_bf16.h>
#include <cstdint>
#include <math.h>

#define B_ 4
#define T_ 2048
#define C_ 1024
#define H_ 16
#define D_ 64

// ---------------------------------------------------------------------------
// Scratch (allocation-free rule: __device__ globals)
// ---------------------------------------------------------------------------
__device__ __nv_bfloat16 g_qkvh[(size_t)B_ * T_ * 3 * C_];   // qkv hi/lo (GEMM epilogue)
__device__ __nv_bfloat16 g_qkvl[(size_t)B_ * T_ * 3 * C_];
__device__ __nv_bfloat16 g_xh[(size_t)B_ * T_ * C_];         // x hi/lo
__device__ __nv_bfloat16 g_xl[(size_t)B_ * T_ * C_];
__device__ __nv_bfloat16 g_yh[(size_t)B_ * T_ * C_];         // y hi/lo (attn output)
__device__ __nv_bfloat16 g_yl[(size_t)B_ * T_ * C_];
__device__ __nv_bfloat16 g_wqh[(size_t)3 * C_ * C_];         // w_qkv hi/lo
__device__ __nv_bfloat16 g_wql[(size_t)3 * C_ * C_];
__device__ __nv_bfloat16 g_woh[(size_t)C_ * C_];             // w_out hi/lo
__device__ __nv_bfloat16 g_wol[(size_t)C_ * C_];

// ---------------------------------------------------------------------------
// Baseline-PTX helpers (all valid on compute_103: no tcgen05)
// ---------------------------------------------------------------------------
__device__ __forceinline__ uint32_t smem_u32(const void* p) {
    uint32_t a;
    asm("{ .reg .u64 t; cvta.to.shared.u64 t, %1; cvt.u32.u64 %0, t; }" : "=r"(a) : "l"(p));
    return a;
}
__device__ __forceinline__ uint32_t swz128(uint32_t off) { return off ^ ((off >> 3) & 0x70); }

__device__ __forceinline__ void cp_async16(uint32_t dst, const void* src) {
    asm volatile("cp.async.cg.shared.global [%0], [%1], 16;" :: "r"(dst), "l"(src) : "memory");
}
#define CP_COMMIT()  asm volatile("cp.async.commit_group;" ::: "memory")
#define CP_WAIT(n)   asm volatile("cp.async.wait_group %0;" :: "n"(n) : "memory")

#define LDSM_X4(r0, r1, r2, r3, addr) \
    asm volatile("ldmatrix.sync.aligned.m8n8.x4.shared.b16 {%0,%1,%2,%3}, [%4];" \
        : "=r"(r0), "=r"(r1), "=r"(r2), "=r"(r3) : "r"(addr))

#define LDSM_X4_T(r0, r1, r2, r3, addr) \
    asm volatile("ldmatrix.sync.aligned.m8n8.x4.trans.shared.b16 {%0,%1,%2,%3}, [%4];" \
        : "=r"(r0), "=r"(r1), "=r"(r2), "=r"(r3) : "r"(addr))

#define MMA16816(d, a, b) \
    asm volatile("mma.sync.aligned.m16n8k16.row.col.f32.bf16.bf16.f32 " \
        "{%0,%1,%2,%3}, {%4,%5,%6,%7}, {%8,%9}, {%0,%1,%2,%3};" \
        : "+f"((d)[0]), "+f"((d)[1]), "+f"((d)[2]), "+f"((d)[3]) \
        : "r"((a)[0]), "r"((a)[1]), "r"((a)[2]), "r"((a)[3]), "r"((b)[0]), "r"((b)[1]))

__device__ __forceinline__ uint32_t pack_bf16x2(float lo, float hi) {
    uint32_t r;
    asm("cvt.rn.bf16x2.f32 %0, %1, %2;" : "=r"(r) : "f"(hi), "f"(lo));
    return r;
}
__device__ __forceinline__ float bf16lo_f(uint32_t p) { return __uint_as_float(p << 16); }
__device__ __forceinline__ float bf16hi_f(uint32_t p) { return __uint_as_float(p & 0xffff0000u); }

// ---------------------------------------------------------------------------
// hi/lo bf16 split of fp32 inputs
// ---------------------------------------------------------------------------
__global__ __launch_bounds__(256) void split_kernel(
    const float* __restrict__ src, __nv_bfloat16* __restrict__ h,
    __nv_bfloat16* __restrict__ l, int n4)
{
    int i = blockIdx.x * 256 + threadIdx.x;
    if (i >= n4) return;
    float4 v = ((const float4*)src)[i];
    uint32_t h01 = pack_bf16x2(v.x, v.y), h23 = pack_bf16x2(v.z, v.w);
    uint32_t l01 = pack_bf16x2(v.x - bf16lo_f(h01), v.y - bf16hi_f(h01));
    uint32_t l23 = pack_bf16x2(v.z - bf16lo_f(h23), v.w - bf16hi_f(h23));
    uint32_t* hp = (uint32_t*)(h + 4 * (size_t)i);
    uint32_t* lp = (uint32_t*)(l + 4 * (size_t)i);
    hp[0] = h01; hp[1] = h23;
    lp[0] = l01; lp[1] = l23;
}

// ---------------------------------------------------------------------------
// cp.async double-buffered mma.sync bf16x3 GEMM:
// OUT[m,n] = sum_k A[m,k]*B[n,k];  D = Ah*Bh + Ah*Bl + Al*Bh
// CTA 128x128, BK=64, 2-stage pipeline (2 x 64KB smem).
// BF16OUT: write bf16 hi/lo pair instead of fp32.
// ---------------------------------------------------------------------------
#define G_STAGE 65536
#define G_AH 0
#define G_AL 16384
#define G_BH 32768
#define G_BL 49152
#define G_TOTAL (2 * G_STAGE)

template <bool BF16OUT>
__global__ __launch_bounds__(256, 1) void gemm_bf16x3(
    const __nv_bfloat16* __restrict__ Ah, const __nv_bfloat16* __restrict__ Al,
    const __nv_bfloat16* __restrict__ Bh, const __nv_bfloat16* __restrict__ Bl,
    float* __restrict__ OUT,
    __nv_bfloat16* __restrict__ OUTH, __nv_bfloat16* __restrict__ OUTL,
    int N, int K)
{
    extern __shared__ char smem[];
    const uint32_t sb = smem_u32(smem);
    const int tid  = threadIdx.x;
    const int lane = tid & 31;
    const int warp = tid >> 5;
    const int wm   = warp >> 1;
    const int wn   = warp & 1;

    const size_t arow0 = (size_t)blockIdx.y * 128;
    const size_t brow0 = (size_t)blockIdx.x * 128;
    const __nv_bfloat16* pAh = Ah + arow0 * K;
    const __nv_bfloat16* pAl = Al + arow0 * K;
    const __nv_bfloat16* pBh = Bh + brow0 * K;
    const __nv_bfloat16* pBl = Bl + brow0 * K;

    const int nchunks = K >> 6;

    auto issue = [&](int ch, int st) {
        const int k0 = ch << 6;
        const uint32_t s0 = sb + st * G_STAGE;
#pragma unroll
        for (int i = 0; i < 4; i++) {
            int ci = tid + i * 256;
            int r = ci >> 3, c = ci & 7;
            uint32_t so = swz128((uint32_t)(r * 128 + c * 16));
            size_t go = (size_t)r * K + k0 + c * 8;
            cp_async16(s0 + G_AH + so, pAh + go);
            cp_async16(s0 + G_AL + so, pAl + go);
            cp_async16(s0 + G_BH + so, pBh + go);
            cp_async16(s0 + G_BL + so, pBl + go);
        }
        CP_COMMIT();
    };

    float acc[2][8][4];
#pragma unroll
    for (int mt = 0; mt < 2; mt++)
#pragma unroll
        for (int nt = 0; nt < 8; nt++)
#pragma unroll
            for (int r = 0; r < 4; r++) acc[mt][nt][r] = 0.f;

    const int a_r  = lane & 15;
    const int a_k  = (lane >> 4) * 8;
    const int b_rr = lane & 7;
    const int b_g  = lane >> 3;
    const int b_n  = ((b_g >> 1) * 8) + b_rr;
    const int b_k  = (b_g & 1) * 8;

    issue(0, 0);

    for (int ch = 0; ch < nchunks; ch++) {
        if (ch + 1 < nchunks) { issue(ch + 1, (ch + 1) & 1); CP_WAIT(1); }
        else                  { CP_WAIT(0); }
        __syncthreads();

        const uint32_t s0 = sb + (ch & 1) * G_STAGE;
#pragma unroll
        for (int ks = 0; ks < 4; ks++) {
            const int kk = ks * 16;
            uint32_t fAh[2][4], fAl[2][4];
#pragma unroll
            for (int mt = 0; mt < 2; mt++) {
                uint32_t bo = swz128((uint32_t)((wm * 32 + mt * 16 + a_r) * 128 + (kk + a_k) * 2));
                LDSM_X4(fAh[mt][0], fAh[mt][1], fAh[mt][2], fAh[mt][3], s0 + G_AH + bo);
                LDSM_X4(fAl[mt][0], fAl[mt][1], fAl[mt][2], fAl[mt][3], s0 + G_AL + bo);
            }
            uint32_t fBh[8][2], fBl[8][2];
#pragma unroll
            for (int p = 0; p < 4; p++) {
                uint32_t bo = swz128((uint32_t)((wn * 64 + p * 16 + b_n) * 128 + (kk + b_k) * 2));
                uint32_t r0, r1, r2, r3;
                LDSM_X4(r0, r1, r2, r3, s0 + G_BH + bo);
                fBh[p*2][0] = r0; fBh[p*2][1] = r1; fBh[p*2+1][0] = r2; fBh[p*2+1][1] = r3;
                LDSM_X4(r0, r1, r2, r3, s0 + G_BL + bo);
                fBl[p*2][0] = r0; fBl[p*2][1] = r1; fBl[p*2+1][0] = r2; fBl[p*2+1][1] = r3;
            }
#pragma unroll
            for (int mt = 0; mt < 2; mt++)
#pragma unroll
                for (int nt = 0; nt < 8; nt++) MMA16816(acc[mt][nt], fAh[mt], fBh[nt]);
#pragma unroll
            for (int mt = 0; mt < 2; mt++)
#pragma unroll
                for (int nt = 0; nt < 8; nt++) MMA16816(acc[mt][nt], fAh[mt], fBl[nt]);
#pragma unroll
            for (int mt = 0; mt < 2; mt++)
#pragma unroll
                for (int nt = 0; nt < 8; nt++) MMA16816(acc[mt][nt], fAl[mt], fBh[nt]);
        }
        __syncthreads();
    }

    const int c_r = lane >> 2;
    const int c_c = (lane & 3) * 2;
#pragma unroll
    for (int mt = 0; mt < 2; mt++) {
        size_t row = arow0 + wm * 32 + mt * 16 + c_r;
        size_t off0 = row * N       + brow0 + wn * 64 + c_c;
        size_t off1 = (row + 8) * N + brow0 + wn * 64 + c_c;
        if (BF16OUT) {
#pragma unroll
            for (int nt = 0; nt < 8; nt++) {
                float y0 = acc[mt][nt][0], y1 = acc[mt][nt][1];
                float y2 = acc[mt][nt][2], y3 = acc[mt][nt][3];
                uint32_t h01 = pack_bf16x2(y0, y1);
                uint32_t l01 = pack_bf16x2(y0 - bf16lo_f(h01), y1 - bf16hi_f(h01));
                uint32_t h23 = pack_bf16x2(y2, y3);
                uint32_t l23 = pack_bf16x2(y2 - bf16lo_f(h23), y3 - bf16hi_f(h23));
                *(uint32_t*)(OUTH + off0 + nt * 8) = h01;
                *(uint32_t*)(OUTL + off0 + nt * 8) = l01;
                *(uint32_t*)(OUTH + off1 + nt * 8) = h23;
                *(uint32_t*)(OUTL + off1 + nt * 8) = l23;
            }
        } else {
#pragma unroll
            for (int nt = 0; nt < 8; nt++) {
                *(float2*)(OUT + off0 + nt * 8) = make_float2(acc[mt][nt][0], acc[mt][nt][1]);
                *(float2*)(OUT + off1 + nt * 8) = make_float2(acc[mt][nt][2], acc[mt][nt][3]);
            }
        }
    }
}

// ---------------------------------------------------------------------------
// Tensor-core causal flash attention, bf16 hi/lo qkv input (no conversion in
// the loop). K smem [key][d]; V smem [key][d] with ldmatrix.trans for V^T
// fragments. cp.async 2-stage K/V pipeline. Scale applied to fp32 S-frags.
// CTA = 128 queries x one (b,h); 8 warps x 16 rows; key blocks of 64.
// ---------------------------------------------------------------------------
#define AQ_H 0
#define AQ_L 16384
#define A_STG 32768          // stage base; per stage: KH 0, KL 8K, VH 16K, VL 24K
#define A_SSZ 32768
#define A_TOTAL (A_STG + 2 * A_SSZ)

__global__ __launch_bounds__(256, 1) void attn_mma(
    const __nv_bfloat16* __restrict__ qkvh, const __nv_bfloat16* __restrict__ qkvl,
    __nv_bfloat16* __restrict__ yh, __nv_bfloat16* __restrict__ yl)
{
    extern __shared__ char smem[];
    const uint32_t sb = smem_u32(smem);
    const int qt   = blockIdx.x;
    const int h    = blockIdx.y;
    const int b    = blockIdx.z;
    const int tid  = threadIdx.x;
    const int lane = tid & 31;
    const int warp = tid >> 5;

    const size_t rs = (size_t)3 * C_;
    const __nv_bfloat16* Qh = qkvh + ((size_t)(b * T_ + qt * 128)) * rs + h * D_;
    const __nv_bfloat16* Ql = qkvl + ((size_t)(b * T_ + qt * 128)) * rs + h * D_;
    const __nv_bfloat16* Kh = qkvh + ((size_t)b * T_) * rs + C_     + h * D_;
    const __nv_bfloat16* Kl = qkvl + ((size_t)b * T_) * rs + C_     + h * D_;
    const __nv_bfloat16* Vh = qkvh + ((size_t)b * T_) * rs + 2 * C_ + h * D_;
    const __nv_bfloat16* Vl = qkvl + ((size_t)b * T_) * rs + 2 * C_ + h * D_;

    // ---- Q tile loads (128 rows x 128B per half) ----
#pragma unroll
    for (int i = 0; i < 4; i++) {
        int lin = i * 256 + tid;                 // 0..1023
        int r = lin >> 3, c = lin & 7;
        uint32_t so = swz128((uint32_t)(r * 128 + c * 16));
        cp_async16(sb + AQ_H + so, Qh + (size_t)r * rs + c * 8);
        cp_async16(sb + AQ_L + so, Ql + (size_t)r * rs + c * 8);
    }
    CP_COMMIT();

    auto issue_blk = [&](int kb, int st) {
        const uint32_t s0 = sb + A_STG + st * A_SSZ;
        const size_t g0 = (size_t)(kb * 64) * rs;
#pragma unroll
        for (int i = 0; i < 2; i++) {
            int lin = i * 256 + tid;             // 0..511
            int r = lin >> 3, c = lin & 7;
            uint32_t so = swz128((uint32_t)(r * 128 + c * 16));
            size_t go = g0 + (size_t)r * rs + c * 8;
            cp_async16(s0 + 0     + so, Kh + go);
            cp_async16(s0 + 8192  + so, Kl + go);
            cp_async16(s0 + 16384 + so, Vh + go);
            cp_async16(s0 + 24576 + so, Vl + go);
        }
        CP_COMMIT();
    };

    issue_blk(0, 0);
    CP_WAIT(1);              // Q group done (block0 may still be in flight)
    __syncthreads();

    // ---- Q fragments (resident) ----
    const int a_r = lane & 15, a_k = (lane >> 4) * 8;
    uint32_t fQh[4][4], fQl[4][4];
#pragma unroll
    for (int ks = 0; ks < 4; ks++) {
        uint32_t bo = swz128((uint32_t)((warp * 16 + a_r) * 128 + (ks * 16 + a_k) * 2));
        LDSM_X4(fQh[ks][0], fQh[ks][1], fQh[ks][2], fQh[ks][3], sb + AQ_H + bo);
        LDSM_X4(fQl[ks][0], fQl[ks][1], fQl[ks][2], fQl[ks][3], sb + AQ_L + bo);
    }

    float oacc[8][4];
#pragma unroll
    for (int j = 0; j < 8; j++)
#pragma unroll
        for (int r = 0; r < 4; r++) oacc[j][r] = 0.f;
    float mrow[2] = {-1e30f, -1e30f};
    float lrow[2] = {0.f, 0.f};

    const int b_rr = lane & 7, b_g = lane >> 3;
    const int b_row = (b_g >> 1) * 8 + b_rr;     // K frags: n row within tile pair
    const int b_k   = (b_g & 1) * 8;             // K frags: k offset
    const int qg0 = qt * 128 + warp * 16 + (lane >> 2);
    const int nb  = 2 * (qt + 1);

    for (int kb = 0; kb < nb; kb++) {
        if (kb + 1 < nb) { issue_blk(kb + 1, (kb + 1) & 1); CP_WAIT(1); }
        else             { CP_WAIT(0); }
        __syncthreads();
        const uint32_t sK = sb + A_STG + (kb & 1) * A_SSZ;
        const uint32_t sV = sK + 16384;

        // ---- S = Q K^T (bf16x3) ----
        float sacc[8][4];
#pragma unroll
        for (int j = 0; j < 8; j++)
#pragma unroll
            for (int r = 0; r < 4; r++) sacc[j][r] = 0.f;
#pragma unroll
        for (int ks = 0; ks < 4; ks++) {
#pragma unroll
            for (int p = 0; p < 4; p++) {
                uint32_t bo = swz128((uint32_t)((p * 16 + b_row) * 128 + (ks * 16 + b_k) * 2));
                uint32_t bh[2][2], bl[2][2], r0, r1, r2, r3;
                LDSM_X4(r0, r1, r2, r3, sK + bo);
                bh[0][0] = r0; bh[0][1] = r1; bh[1][0] = r2; bh[1][1] = r3;
                LDSM_X4(r0, r1, r2, r3, sK + 8192 + bo);
                bl[0][0] = r0; bl[0][1] = r1; bl[1][0] = r2; bl[1][1] = r3;
                MMA16816(sacc[2*p],   fQh[ks], bh[0]);
                MMA16816(sacc[2*p+1], fQh[ks], bh[1]);
                MMA16816(sacc[2*p],   fQh[ks], bl[0]);
                MMA16816(sacc[2*p+1], fQh[ks], bl[1]);
                MMA16816(sacc[2*p],   fQl[ks], bh[0]);
                MMA16816(sacc[2*p+1], fQl[ks], bh[1]);
            }
        }

        // ---- scale + causal mask ----
#pragma unroll
        for (int j = 0; j < 8; j++)
#pragma unroll
            for (int r = 0; r < 4; r++) sacc[j][r] *= 0.125f;
        if (kb >= 2 * qt) {
            const int kbase = kb * 64 + (lane & 3) * 2;
#pragma unroll
            for (int j = 0; j < 8; j++) {
#pragma unroll
                for (int cc = 0; cc < 2; cc++) {
                    int kg = kbase + j * 8 + cc;
                    if (kg > qg0)     sacc[j][cc]     = -1e30f;
                    if (kg > qg0 + 8) sacc[j][2 + cc] = -1e30f;
                }
            }
        }

        // ---- online softmax ----
        float m0 = mrow[0], m1 = mrow[1];
#pragma unroll
        for (int j = 0; j < 8; j++) {
            m0 = fmaxf(m0, fmaxf(sacc[j][0], sacc[j][1]));
            m1 = fmaxf(m1, fmaxf(sacc[j][2], sacc[j][3]));
        }
        m0 = fmaxf(m0, __shfl_xor_sync(0xffffffffu, m0, 1));
        m0 = fmaxf(m0, __shfl_xor_sync(0xffffffffu, m0, 2));
        m1 = fmaxf(m1, __shfl_xor_sync(0xffffffffu, m1, 1));
        m1 = fmaxf(m1, __shfl_xor_sync(0xffffffffu, m1, 2));
        const float f0 = __expf(mrow[0] - m0), f1 = __expf(mrow[1] - m1);
        mrow[0] = m0; mrow[1] = m1;
        lrow[0] *= f0; lrow[1] *= f1;
#pragma unroll
        for (int j = 0; j < 8; j++) {
            oacc[j][0] *= f0; oacc[j][1] *= f0;
            oacc[j][2] *= f1; oacc[j][3] *= f1;
        }

        uint32_t ah[4][4], al[4][4];
#pragma unroll
        for (int j = 0; j < 8; j++) {
            float p0 = __expf(sacc[j][0] - m0);
            float p1 = __expf(sacc[j][1] - m0);
            float p2 = __expf(sacc[j][2] - m1);
            float p3 = __expf(sacc[j][3] - m1);
            lrow[0] += p0 + p1;
            lrow[1] += p2 + p3;
            uint32_t ph01 = pack_bf16x2(p0, p1);
            uint32_t ph23 = pack_bf16x2(p2, p3);
            uint32_t pl01 = pack_bf16x2(p0 - bf16lo_f(ph01), p1 - bf16hi_f(ph01));
            uint32_t pl23 = pack_bf16x2(p2 - bf16lo_f(ph23), p3 - bf16hi_f(ph23));
            const int ks = j >> 1, sl = (j & 1) * 2;
            ah[ks][sl]     = ph01;  ah[ks][sl + 1] = ph23;
            al[ks][sl]     = pl01;  al[ks][sl + 1] = pl23;
        }

        // ---- O += P V : V^T fragments via ldmatrix.trans on [key][d] tile ----
#pragma unroll
        for (int ks = 0; ks < 4; ks++) {
#pragma unroll
            for (int p = 0; p < 4; p++) {
                // lane addr: row = key = ks*16 + (g&1)*8 + rr ; col = d = p*16 + (g>>1)*8
                uint32_t bo = swz128((uint32_t)((ks * 16 + (b_g & 1) * 8 + b_rr) * 128 +
                                                (p * 16 + (b_g >> 1) * 8) * 2));
                uint32_t vh[2][2], vl[2][2], r0, r1, r2, r3;
                LDSM_X4_T(r0, r1, r2, r3, sV + bo);
                vh[0][0] = r0; vh[0][1] = r1; vh[1][0] = r2; vh[1][1] = r3;
                LDSM_X4_T(r0, r1, r2, r3, sV + 8192 + bo);
                vl[0][0] = r0; vl[0][1] = r1; vl[1][0] = r2; vl[1][1] = r3;
                MMA16816(oacc[2*p],   ah[ks], vh[0]);
                MMA16816(oacc[2*p+1], ah[ks], vh[1]);
                MMA16816(oacc[2*p],   ah[ks], vl[0]);
                MMA16816(oacc[2*p+1], ah[ks], vl[1]);
                MMA16816(oacc[2*p],   al[ks], vh[0]);
                MMA16816(oacc[2*p+1], al[ks], vh[1]);
            }
        }
        __syncthreads();
    }

    // ---- finalize ----
    lrow[0] += __shfl_xor_sync(0xffffffffu, lrow[0], 1);
    lrow[0] += __shfl_xor_sync(0xffffffffu, lrow[0], 2);
    lrow[1] += __shfl_xor_sync(0xffffffffu, lrow[1], 1);
    lrow[1] += __shfl_xor_sync(0xffffffffu, lrow[1], 2);
    const float inv0 = 1.f / lrow[0], inv1 = 1.f / lrow[1];

    const int t0 = qt * 128 + warp * 16 + (lane >> 2);
    const size_t base0 = ((size_t)(b * T_ + t0)) * C_ + h * D_ + (lane & 3) * 2;
    const size_t base1 = base0 + 8 * (size_t)C_;
#pragma unroll
    for (int j = 0; j < 8; j++) {
        float y0 = oacc[j][0] * inv0, y1 = oacc[j][1] * inv0;
        float y2 = oacc[j][2] * inv1, y3 = oacc[j][3] * inv1;
        uint32_t h01 = pack_bf16x2(y0, y1);
        uint32_t l01 = pack_bf16x2(y0 - bf16lo_f(h01), y1 - bf16hi_f(h01));
        uint32_t h23 = pack_bf16x2(y2, y3);
        uint32_t l23 = pack_bf16x2(y2 - bf16lo_f(h23), y3 - bf16hi_f(h23));
        *(uint32_t*)(yh + base0 + j * 8) = h01;
        *(uint32_t*)(yl + base0 + j * 8) = l01;
        *(uint32_t*)(yh + base1 + j * 8) = h23;
        *(uint32_t*)(yl + base1 + j * 8) = l23;
    }
}

// ---------------------------------------------------------------------------
extern "C" void kernel_launch(void* const* d_in, const int* in_sizes, int n_in,
                              void* d_out, int out_size)
{
    const float* x     = (const float*)d_in[0];   // [B,T,C]
    const float* w_qkv = (const float*)d_in[1];   // [3C,C]
    const float* w_out = (const float*)d_in[2];   // [C,C]
    float* out = (float*)d_out;                   // [B,T,C]

    __nv_bfloat16 *qkvh, *qkvl, *xh, *xl, *yh, *yl, *wqh, *wql, *woh, *wol;
    cudaGetSymbolAddress((void**)&qkvh, g_qkvh); cudaGetSymbolAddress((void**)&qkvl, g_qkvl);
    cudaGetSymbolAddress((void**)&xh,  g_xh);  cudaGetSymbolAddress((void**)&xl,  g_xl);
    cudaGetSymbolAddress((void**)&yh,  g_yh);  cudaGetSymbolAddress((void**)&yl,  g_yl);
    cudaGetSymbolAddress((void**)&wqh, g_wqh); cudaGetSymbolAddress((void**)&wql, g_wql);
    cudaGetSymbolAddress((void**)&woh, g_woh); cudaGetSymbolAddress((void**)&wol, g_wol);

    cudaFuncSetAttribute(gemm_bf16x3<true>,  cudaFuncAttributeMaxDynamicSharedMemorySize, G_TOTAL);
    cudaFuncSetAttribute(gemm_bf16x3<false>, cudaFuncAttributeMaxDynamicSharedMemorySize, G_TOTAL);
    cudaFuncSetAttribute(attn_mma,           cudaFuncAttributeMaxDynamicSharedMemorySize, A_TOTAL);

    const int M = B_ * T_;                  // 8192
    const int n_x  = M * C_;
    const int n_wq = 3 * C_ * C_;
    const int n_wo = C_ * C_;

    split_kernel<<<(n_x / 4 + 255) / 256, 256>>>(x, xh, xl, n_x / 4);
    split_kernel<<<(n_wq / 4 + 255) / 256, 256>>>(w_qkv, wqh, wql, n_wq / 4);
    split_kernel<<<(n_wo / 4 + 255) / 256, 256>>>(w_out, woh, wol, n_wo / 4);

    // 1) qkv = x @ w_qkv^T -> bf16 hi/lo directly
    {
        dim3 grid(3 * C_ / 128, M / 128);
        gemm_bf16x3<true><<<grid, 256, G_TOTAL>>>(xh, xl, wqh, wql,
                                                  nullptr, qkvh, qkvl, 3 * C_, C_);
    }
    // 2) causal attention (bf16 in, bf16 hi/lo out)
    {
        dim3 grid(T_ / 128, H_, B_);
        attn_mma<<<grid, 256, A_TOTAL>>>(qkvh, qkvl, yh, yl);
    }
    // 3) out = y @ w_out^T -> fp32
    {
        dim3 grid(C_ / 128, M / 128);
        gemm_bf16x3<false><<<grid, 256, G_TOTAL>>>(yh, yl, woh, wol,
                                                   out, nullptr, nullptr, C_, C_);
    }
}

// round 11
// speedup vs baseline: 4.7041x; 1.0022x over previous
#include <cuda_runtime.h>
#include <cuda_bf16.h>
#include <cstdint>
#include <math.h>

#define B_ 4
#define T_ 2048
#define C_ 1024
#define H_ 16
#define D_ 64

// ---------------------------------------------------------------------------
// Scratch (allocation-free rule: __device__ globals)
// ---------------------------------------------------------------------------
__device__ __nv_bfloat16 g_qkvh[(size_t)B_ * T_ * 3 * C_];   // qkv hi/lo (GEMM epilogue)
__device__ __nv_bfloat16 g_qkvl[(size_t)B_ * T_ * 3 * C_];
__device__ __nv_bfloat16 g_xh[(size_t)B_ * T_ * C_];         // x hi/lo
__device__ __nv_bfloat16 g_xl[(size_t)B_ * T_ * C_];
__device__ __nv_bfloat16 g_yh[(size_t)B_ * T_ * C_];         // y hi/lo (attn output)
__device__ __nv_bfloat16 g_yl[(size_t)B_ * T_ * C_];
__device__ __nv_bfloat16 g_wqh[(size_t)3 * C_ * C_];         // w_qkv hi/lo
__device__ __nv_bfloat16 g_wql[(size_t)3 * C_ * C_];
__device__ __nv_bfloat16 g_woh[(size_t)C_ * C_];             // w_out hi/lo
__device__ __nv_bfloat16 g_wol[(size_t)C_ * C_];

// ---------------------------------------------------------------------------
// Baseline-PTX helpers (all valid on compute_103: no tcgen05)
// ---------------------------------------------------------------------------
__device__ __forceinline__ uint32_t smem_u32(const void* p) {
    uint32_t a;
    asm("{ .reg .u64 t; cvta.to.shared.u64 t, %1; cvt.u32.u64 %0, t; }" : "=r"(a) : "l"(p));
    return a;
}
__device__ __forceinline__ uint32_t swz128(uint32_t off) { return off ^ ((off >> 3) & 0x70); }

__device__ __forceinline__ void cp_async16(uint32_t dst, const void* src) {
    asm volatile("cp.async.cg.shared.global [%0], [%1], 16;" :: "r"(dst), "l"(src) : "memory");
}
#define CP_COMMIT()  asm volatile("cp.async.commit_group;" ::: "memory")
#define CP_WAIT(n)   asm volatile("cp.async.wait_group %0;" :: "n"(n) : "memory")

#define LDSM_X4(r0, r1, r2, r3, addr) \
    asm volatile("ldmatrix.sync.aligned.m8n8.x4.shared.b16 {%0,%1,%2,%3}, [%4];" \
        : "=r"(r0), "=r"(r1), "=r"(r2), "=r"(r3) : "r"(addr))

#define LDSM_X4_T(r0, r1, r2, r3, addr) \
    asm volatile("ldmatrix.sync.aligned.m8n8.x4.trans.shared.b16 {%0,%1,%2,%3}, [%4];" \
        : "=r"(r0), "=r"(r1), "=r"(r2), "=r"(r3) : "r"(addr))

#define MMA16816(d, a, b) \
    asm volatile("mma.sync.aligned.m16n8k16.row.col.f32.bf16.bf16.f32 " \
        "{%0,%1,%2,%3}, {%4,%5,%6,%7}, {%8,%9}, {%0,%1,%2,%3};" \
        : "+f"((d)[0]), "+f"((d)[1]), "+f"((d)[2]), "+f"((d)[3]) \
        : "r"((a)[0]), "r"((a)[1]), "r"((a)[2]), "r"((a)[3]), "r"((b)[0]), "r"((b)[1]))

__device__ __forceinline__ uint32_t pack_bf16x2(float lo, float hi) {
    uint32_t r;
    asm("cvt.rn.bf16x2.f32 %0, %1, %2;" : "=r"(r) : "f"(hi), "f"(lo));
    return r;
}
__device__ __forceinline__ float bf16lo_f(uint32_t p) { return __uint_as_float(p << 16); }
__device__ __forceinline__ float bf16hi_f(uint32_t p) { return __uint_as_float(p & 0xffff0000u); }

// ---------------------------------------------------------------------------
// hi/lo bf16 split of fp32 inputs
// ---------------------------------------------------------------------------
__global__ __launch_bounds__(256) void split_kernel(
    const float* __restrict__ src, __nv_bfloat16* __restrict__ h,
    __nv_bfloat16* __restrict__ l, int n4)
{
    int i = blockIdx.x * 256 + threadIdx.x;
    if (i >= n4) return;
    float4 v = ((const float4*)src)[i];
    uint32_t h01 = pack_bf16x2(v.x, v.y), h23 = pack_bf16x2(v.z, v.w);
    uint32_t l01 = pack_bf16x2(v.x - bf16lo_f(h01), v.y - bf16hi_f(h01));
    uint32_t l23 = pack_bf16x2(v.z - bf16lo_f(h23), v.w - bf16hi_f(h23));
    uint32_t* hp = (uint32_t*)(h + 4 * (size_t)i);
    uint32_t* lp = (uint32_t*)(l + 4 * (size_t)i);
    hp[0] = h01; hp[1] = h23;
    lp[0] = l01; lp[1] = l23;
}

// ---------------------------------------------------------------------------
// cp.async 3-stage mma.sync bf16x3 GEMM, one barrier per chunk:
// OUT[m,n] = sum_k A[m,k]*B[n,k];  D = Ah*Bh + Ah*Bl + Al*Bh
// ---------------------------------------------------------------------------
#define G_STAGE 65536
#define G_AH 0
#define G_AL 16384
#define G_BH 32768
#define G_BL 49152
#define G_TOTAL (3 * G_STAGE)

template <bool BF16OUT>
__global__ __launch_bounds__(256, 1) void gemm_bf16x3(
    const __nv_bfloat16* __restrict__ Ah, const __nv_bfloat16* __restrict__ Al,
    const __nv_bfloat16* __restrict__ Bh, const __nv_bfloat16* __restrict__ Bl,
    float* __restrict__ OUT,
    __nv_bfloat16* __restrict__ OUTH, __nv_bfloat16* __restrict__ OUTL,
    int N, int K)
{
    extern __shared__ char smem[];
    const uint32_t sb = smem_u32(smem);
    const int tid  = threadIdx.x;
    const int lane = tid & 31;
    const int warp = tid >> 5;
    const int wm   = warp >> 1;
    const int wn   = warp & 1;

    const size_t arow0 = (size_t)blockIdx.y * 128;
    const size_t brow0 = (size_t)blockIdx.x * 128;
    const __nv_bfloat16* pAh = Ah + arow0 * K;
    const __nv_bfloat16* pAl = Al + arow0 * K;
    const __nv_bfloat16* pBh = Bh + brow0 * K;
    const __nv_bfloat16* pBl = Bl + brow0 * K;

    const int nchunks = K >> 6;

    auto issue = [&](int ch) {
        const int k0 = ch << 6;
        const uint32_t s0 = sb + (ch % 3) * G_STAGE;
#pragma unroll
        for (int i = 0; i < 4; i++) {
            int ci = tid + i * 256;
            int r = ci >> 3, c = ci & 7;
            uint32_t so = swz128((uint32_t)(r * 128 + c * 16));
            size_t go = (size_t)r * K + k0 + c * 8;
            cp_async16(s0 + G_AH + so, pAh + go);
            cp_async16(s0 + G_AL + so, pAl + go);
            cp_async16(s0 + G_BH + so, pBh + go);
            cp_async16(s0 + G_BL + so, pBl + go);
        }
        CP_COMMIT();
    };

    float acc[2][8][4];
#pragma unroll
    for (int mt = 0; mt < 2; mt++)
#pragma unroll
        for (int nt = 0; nt < 8; nt++)
#pragma unroll
            for (int r = 0; r < 4; r++) acc[mt][nt][r] = 0.f;

    const int a_r  = lane & 15;
    const int a_k  = (lane >> 4) * 8;
    const int b_rr = lane & 7;
    const int b_g  = lane >> 3;
    const int b_n  = ((b_g >> 1) * 8) + b_rr;
    const int b_k  = (b_g & 1) * 8;

    issue(0);
    issue(1);                          // nchunks >= 2 always (K >= 128)

    for (int ch = 0; ch < nchunks; ch++) {
        if (ch + 1 < nchunks) CP_WAIT(1); else CP_WAIT(0);
        __syncthreads();               // stage ch published to all warps
        if (ch + 2 < nchunks) issue(ch + 2);   // safe: stage (ch-1)%3 fully consumed

        const uint32_t s0 = sb + (ch % 3) * G_STAGE;
#pragma unroll
        for (int ks = 0; ks < 4; ks++) {
            const int kk = ks * 16;
            uint32_t fAh[2][4], fAl[2][4];
#pragma unroll
            for (int mt = 0; mt < 2; mt++) {
                uint32_t bo = swz128((uint32_t)((wm * 32 + mt * 16 + a_r) * 128 + (kk + a_k) * 2));
                LDSM_X4(fAh[mt][0], fAh[mt][1], fAh[mt][2], fAh[mt][3], s0 + G_AH + bo);
                LDSM_X4(fAl[mt][0], fAl[mt][1], fAl[mt][2], fAl[mt][3], s0 + G_AL + bo);
            }
            uint32_t fBh[8][2], fBl[8][2];
#pragma unroll
            for (int p = 0; p < 4; p++) {
                uint32_t bo = swz128((uint32_t)((wn * 64 + p * 16 + b_n) * 128 + (kk + b_k) * 2));
                uint32_t r0, r1, r2, r3;
                LDSM_X4(r0, r1, r2, r3, s0 + G_BH + bo);
                fBh[p*2][0] = r0; fBh[p*2][1] = r1; fBh[p*2+1][0] = r2; fBh[p*2+1][1] = r3;
                LDSM_X4(r0, r1, r2, r3, s0 + G_BL + bo);
                fBl[p*2][0] = r0; fBl[p*2][1] = r1; fBl[p*2+1][0] = r2; fBl[p*2+1][1] = r3;
            }
#pragma unroll
            for (int mt = 0; mt < 2; mt++)
#pragma unroll
                for (int nt = 0; nt < 8; nt++) MMA16816(acc[mt][nt], fAh[mt], fBh[nt]);
#pragma unroll
            for (int mt = 0; mt < 2; mt++)
#pragma unroll
                for (int nt = 0; nt < 8; nt++) MMA16816(acc[mt][nt], fAh[mt], fBl[nt]);
#pragma unroll
            for (int mt = 0; mt < 2; mt++)
#pragma unroll
                for (int nt = 0; nt < 8; nt++) MMA16816(acc[mt][nt], fAl[mt], fBh[nt]);
        }
        // no trailing barrier: next iteration's leading barrier covers reuse
    }

    const int c_r = lane >> 2;
    const int c_c = (lane & 3) * 2;
#pragma unroll
    for (int mt = 0; mt < 2; mt++) {
        size_t row = arow0 + wm * 32 + mt * 16 + c_r;
        size_t off0 = row * N       + brow0 + wn * 64 + c_c;
        size_t off1 = (row + 8) * N + brow0 + wn * 64 + c_c;
        if (BF16OUT) {
#pragma unroll
            for (int nt = 0; nt < 8; nt++) {
                float y0 = acc[mt][nt][0], y1 = acc[mt][nt][1];
                float y2 = acc[mt][nt][2], y3 = acc[mt][nt][3];
                uint32_t h01 = pack_bf16x2(y0, y1);
                uint32_t l01 = pack_bf16x2(y0 - bf16lo_f(h01), y1 - bf16hi_f(h01));
                uint32_t h23 = pack_bf16x2(y2, y3);
                uint32_t l23 = pack_bf16x2(y2 - bf16lo_f(h23), y3 - bf16hi_f(h23));
                *(uint32_t*)(OUTH + off0 + nt * 8) = h01;
                *(uint32_t*)(OUTL + off0 + nt * 8) = l01;
                *(uint32_t*)(OUTH + off1 + nt * 8) = h23;
                *(uint32_t*)(OUTL + off1 + nt * 8) = l23;
            }
        } else {
#pragma unroll
            for (int nt = 0; nt < 8; nt++) {
                *(float2*)(OUT + off0 + nt * 8) = make_float2(acc[mt][nt][0], acc[mt][nt][1]);
                *(float2*)(OUT + off1 + nt * 8) = make_float2(acc[mt][nt][2], acc[mt][nt][3]);
            }
        }
    }
}

// ---------------------------------------------------------------------------
// Tensor-core causal flash attention, bf16 hi/lo qkv input.
// 3-stage cp.async K/V pipeline, one barrier per key block.
// ---------------------------------------------------------------------------
#define AQ_H 0
#define AQ_L 16384
#define A_STG 32768          // stage base; per stage: KH 0, KL 8K, VH 16K, VL 24K
#define A_SSZ 32768
#define A_TOTAL (A_STG + 3 * A_SSZ)

__global__ __launch_bounds__(256, 1) void attn_mma(
    const __nv_bfloat16* __restrict__ qkvh, const __nv_bfloat16* __restrict__ qkvl,
    __nv_bfloat16* __restrict__ yh, __nv_bfloat16* __restrict__ yl)
{
    extern __shared__ char smem[];
    const uint32_t sb = smem_u32(smem);
    const int qt   = blockIdx.x;
    const int h    = blockIdx.y;
    const int b    = blockIdx.z;
    const int tid  = threadIdx.x;
    const int lane = tid & 31;
    const int warp = tid >> 5;

    const size_t rs = (size_t)3 * C_;
    const __nv_bfloat16* Qh = qkvh + ((size_t)(b * T_ + qt * 128)) * rs + h * D_;
    const __nv_bfloat16* Ql = qkvl + ((size_t)(b * T_ + qt * 128)) * rs + h * D_;
    const __nv_bfloat16* Kh = qkvh + ((size_t)b * T_) * rs + C_     + h * D_;
    const __nv_bfloat16* Kl = qkvl + ((size_t)b * T_) * rs + C_     + h * D_;
    const __nv_bfloat16* Vh = qkvh + ((size_t)b * T_) * rs + 2 * C_ + h * D_;
    const __nv_bfloat16* Vl = qkvl + ((size_t)b * T_) * rs + 2 * C_ + h * D_;

    // ---- Q tile loads ----
#pragma unroll
    for (int i = 0; i < 4; i++) {
        int lin = i * 256 + tid;
        int r = lin >> 3, c = lin & 7;
        uint32_t so = swz128((uint32_t)(r * 128 + c * 16));
        cp_async16(sb + AQ_H + so, Qh + (size_t)r * rs + c * 8);
        cp_async16(sb + AQ_L + so, Ql + (size_t)r * rs + c * 8);
    }
    CP_COMMIT();

    auto issue_blk = [&](int kb) {
        const uint32_t s0 = sb + A_STG + (kb % 3) * A_SSZ;
        const size_t g0 = (size_t)(kb * 64) * rs;
#pragma unroll
        for (int i = 0; i < 2; i++) {
            int lin = i * 256 + tid;
            int r = lin >> 3, c = lin & 7;
            uint32_t so = swz128((uint32_t)(r * 128 + c * 16));
            size_t go = g0 + (size_t)r * rs + c * 8;
            cp_async16(s0 + 0     + so, Kh + go);
            cp_async16(s0 + 8192  + so, Kl + go);
            cp_async16(s0 + 16384 + so, Vh + go);
            cp_async16(s0 + 24576 + so, Vl + go);
        }
        CP_COMMIT();
    };

    const int nb = 2 * (qt + 1);       // >= 2 always
    issue_blk(0);
    CP_WAIT(1);                        // Q done (blk0 may be in flight)
    __syncthreads();

    // ---- Q fragments (resident) ----
    const int a_r = lane & 15, a_k = (lane >> 4) * 8;
    uint32_t fQh[4][4], fQl[4][4];
#pragma unroll
    for (int ks = 0; ks < 4; ks++) {
        uint32_t bo = swz128((uint32_t)((warp * 16 + a_r) * 128 + (ks * 16 + a_k) * 2));
        LDSM_X4(fQh[ks][0], fQh[ks][1], fQh[ks][2], fQh[ks][3], sb + AQ_H + bo);
        LDSM_X4(fQl[ks][0], fQl[ks][1], fQl[ks][2], fQl[ks][3], sb + AQ_L + bo);
    }
    issue_blk(1);

    float oacc[8][4];
#pragma unroll
    for (int j = 0; j < 8; j++)
#pragma unroll
        for (int r = 0; r < 4; r++) oacc[j][r] = 0.f;
    float mrow[2] = {-1e30f, -1e30f};
    float lrow[2] = {0.f, 0.f};

    const int b_rr = lane & 7, b_g = lane >> 3;
    const int b_row = (b_g >> 1) * 8 + b_rr;
    const int b_k   = (b_g & 1) * 8;
    const int qg0 = qt * 128 + warp * 16 + (lane >> 2);

    for (int kb = 0; kb < nb; kb++) {
        if (kb + 1 < nb) CP_WAIT(1); else CP_WAIT(0);
        __syncthreads();               // stage kb published
        if (kb + 2 < nb) issue_blk(kb + 2);   // stage (kb-1)%3 fully consumed

        const uint32_t sK = sb + A_STG + (kb % 3) * A_SSZ;
        const uint32_t sV = sK + 16384;

        // ---- S = Q K^T (bf16x3) ----
        float sacc[8][4];
#pragma unroll
        for (int j = 0; j < 8; j++)
#pragma unroll
            for (int r = 0; r < 4; r++) sacc[j][r] = 0.f;
#pragma unroll
        for (int ks = 0; ks < 4; ks++) {
#pragma unroll
            for (int p = 0; p < 4; p++) {
                uint32_t bo = swz128((uint32_t)((p * 16 + b_row) * 128 + (ks * 16 + b_k) * 2));
                uint32_t bh[2][2], bl[2][2], r0, r1, r2, r3;
                LDSM_X4(r0, r1, r2, r3, sK + bo);
                bh[0][0] = r0; bh[0][1] = r1; bh[1][0] = r2; bh[1][1] = r3;
                LDSM_X4(r0, r1, r2, r3, sK + 8192 + bo);
                bl[0][0] = r0; bl[0][1] = r1; bl[1][0] = r2; bl[1][1] = r3;
                MMA16816(sacc[2*p],   fQh[ks], bh[0]);
                MMA16816(sacc[2*p+1], fQh[ks], bh[1]);
                MMA16816(sacc[2*p],   fQh[ks], bl[0]);
                MMA16816(sacc[2*p+1], fQh[ks], bl[1]);
                MMA16816(sacc[2*p],   fQl[ks], bh[0]);
                MMA16816(sacc[2*p+1], fQl[ks], bh[1]);
            }
        }

        // ---- scale + causal mask ----
#pragma unroll
        for (int j = 0; j < 8; j++)
#pragma unroll
            for (int r = 0; r < 4; r++) sacc[j][r] *= 0.125f;
        if (kb >= 2 * qt) {
            const int kbase = kb * 64 + (lane & 3) * 2;
#pragma unroll
            for (int j = 0; j < 8; j++) {
#pragma unroll
                for (int cc = 0; cc < 2; cc++) {
                    int kg = kbase + j * 8 + cc;
                    if (kg > qg0)     sacc[j][cc]     = -1e30f;
                    if (kg > qg0 + 8) sacc[j][2 + cc] = -1e30f;
                }
            }
        }

        // ---- online softmax ----
        float m0 = mrow[0], m1 = mrow[1];
#pragma unroll
        for (int j = 0; j < 8; j++) {
            m0 = fmaxf(m0, fmaxf(sacc[j][0], sacc[j][1]));
            m1 = fmaxf(m1, fmaxf(sacc[j][2], sacc[j][3]));
        }
        m0 = fmaxf(m0, __shfl_xor_sync(0xffffffffu, m0, 1));
        m0 = fmaxf(m0, __shfl_xor_sync(0xffffffffu, m0, 2));
        m1 = fmaxf(m1, __shfl_xor_sync(0xffffffffu, m1, 1));
        m1 = fmaxf(m1, __shfl_xor_sync(0xffffffffu, m1, 2));
        const float f0 = __expf(mrow[0] - m0), f1 = __expf(mrow[1] - m1);
        mrow[0] = m0; mrow[1] = m1;
        lrow[0] *= f0; lrow[1] *= f1;
#pragma unroll
        for (int j = 0; j < 8; j++) {
            oacc[j][0] *= f0; oacc[j][1] *= f0;
            oacc[j][2] *= f1; oacc[j][3] *= f1;
        }

        uint32_t ah[4][4], al[4][4];
#pragma unroll
        for (int j = 0; j < 8; j++) {
            float p0 = __expf(sacc[j][0] - m0);
            float p1 = __expf(sacc[j][1] - m0);
            float p2 = __expf(sacc[j][2] - m1);
            float p3 = __expf(sacc[j][3] - m1);
            lrow[0] += p0 + p1;
            lrow[1] += p2 + p3;
            uint32_t ph01 = pack_bf16x2(p0, p1);
            uint32_t ph23 = pack_bf16x2(p2, p3);
            uint32_t pl01 = pack_bf16x2(p0 - bf16lo_f(ph01), p1 - bf16hi_f(ph01));
            uint32_t pl23 = pack_bf16x2(p2 - bf16lo_f(ph23), p3 - bf16hi_f(ph23));
            const int ks = j >> 1, sl = (j & 1) * 2;
            ah[ks][sl]     = ph01;  ah[ks][sl + 1] = ph23;
            al[ks][sl]     = pl01;  al[ks][sl + 1] = pl23;
        }

        // ---- O += P V (V^T frags via ldmatrix.trans) ----
#pragma unroll
        for (int ks = 0; ks < 4; ks++) {
#pragma unroll
            for (int p = 0; p < 4; p++) {
                uint32_t bo = swz128((uint32_t)((ks * 16 + (b_g & 1) * 8 + b_rr) * 128 +
                                                (p * 16 + (b_g >> 1) * 8) * 2));
                uint32_t vh[2][2], vl[2][2], r0, r1, r2, r3;
                LDSM_X4_T(r0, r1, r2, r3, sV + bo);
                vh[0][0] = r0; vh[0][1] = r1; vh[1][0] = r2; vh[1][1] = r3;
                LDSM_X4_T(r0, r1, r2, r3, sV + 8192 + bo);
                vl[0][0] = r0; vl[0][1] = r1; vl[1][0] = r2; vl[1][1] = r3;
                MMA16816(oacc[2*p],   ah[ks], vh[0]);
                MMA16816(oacc[2*p+1], ah[ks], vh[1]);
                MMA16816(oacc[2*p],   ah[ks], vl[0]);
                MMA16816(oacc[2*p+1], ah[ks], vl[1]);
                MMA16816(oacc[2*p],   al[ks], vh[0]);
                MMA16816(oacc[2*p+1], al[ks], vh[1]);
            }
        }
        // no trailing barrier (3-stage ring)
    }

    // ---- finalize ----
    lrow[0] += __shfl_xor_sync(0xffffffffu, lrow[0], 1);
    lrow[0] += __shfl_xor_sync(0xffffffffu, lrow[0], 2);
    lrow[1] += __shfl_xor_sync(0xffffffffu, lrow[1], 1);
    lrow[1] += __shfl_xor_sync(0xffffffffu, lrow[1], 2);
    const float inv0 = 1.f / lrow[0], inv1 = 1.f / lrow[1];

    const int t0 = qt * 128 + warp * 16 + (lane >> 2);
    const size_t base0 = ((size_t)(b * T_ + t0)) * C_ + h * D_ + (lane & 3) * 2;
    const size_t base1 = base0 + 8 * (size_t)C_;
#pragma unroll
    for (int j = 0; j < 8; j++) {
        float y0 = oacc[j][0] * inv0, y1 = oacc[j][1] * inv0;
        float y2 = oacc[j][2] * inv1, y3 = oacc[j][3] * inv1;
        uint32_t h01 = pack_bf16x2(y0, y1);
        uint32_t l01 = pack_bf16x2(y0 - bf16lo_f(h01), y1 - bf16hi_f(h01));
        uint32_t h23 = pack_bf16x2(y2, y3);
        uint32_t l23 = pack_bf16x2(y2 - bf16lo_f(h23), y3 - bf16hi_f(h23));
        *(uint32_t*)(yh + base0 + j * 8) = h01;
        *(uint32_t*)(yl + base0 + j * 8) = l01;
        *(uint32_t*)(yh + base1 + j * 8) = h23;
        *(uint32_t*)(yl + base1 + j * 8) = l23;
    }
}

// ---------------------------------------------------------------------------
extern "C" void kernel_launch(void* const* d_in, const int* in_sizes, int n_in,
                              void* d_out, int out_size)
{
    const float* x     = (const float*)d_in[0];   // [B,T,C]
    const float* w_qkv = (const float*)d_in[1];   // [3C,C]
    const float* w_out = (const float*)d_in[2];   // [C,C]
    float* out = (float*)d_out;                   // [B,T,C]

    __nv_bfloat16 *qkvh, *qkvl, *xh, *xl, *yh, *yl, *wqh, *wql, *woh, *wol;
    cudaGetSymbolAddress((void**)&qkvh, g_qkvh); cudaGetSymbolAddress((void**)&qkvl, g_qkvl);
    cudaGetSymbolAddress((void**)&xh,  g_xh);  cudaGetSymbolAddress((void**)&xl,  g_xl);
    cudaGetSymbolAddress((void**)&yh,  g_yh);  cudaGetSymbolAddress((void**)&yl,  g_yl);
    cudaGetSymbolAddress((void**)&wqh, g_wqh); cudaGetSymbolAddress((void**)&wql, g_wql);
    cudaGetSymbolAddress((void**)&woh, g_woh); cudaGetSymbolAddress((void**)&wol, g_wol);

    cudaFuncSetAttribute(gemm_bf16x3<true>,  cudaFuncAttributeMaxDynamicSharedMemorySize, G_TOTAL);
    cudaFuncSetAttribute(gemm_bf16x3<false>, cudaFuncAttributeMaxDynamicSharedMemorySize, G_TOTAL);
    cudaFuncSetAttribute(attn_mma,           cudaFuncAttributeMaxDynamicSharedMemorySize, A_TOTAL);

    const int M = B_ * T_;                  // 8192
    const int n_x  = M * C_;
    const int n_wq = 3 * C_ * C_;
    const int n_wo = C_ * C_;

    split_kernel<<<(n_x / 4 + 255) / 256, 256>>>(x, xh, xl, n_x / 4);
    split_kernel<<<(n_wq / 4 + 255) / 256, 256>>>(w_qkv, wqh, wql, n_wq / 4);
    split_kernel<<<(n_wo / 4 + 255) / 256, 256>>>(w_out, woh, wol, n_wo / 4);

    // 1) qkv = x @ w_qkv^T -> bf16 hi/lo directly
    {
        dim3 grid(3 * C_ / 128, M / 128);
        gemm_bf16x3<true><<<grid, 256, G_TOTAL>>>(xh, xl, wqh, wql,
                                                  nullptr, qkvh, qkvl, 3 * C_, C_);
    }
    // 2) causal attention (bf16 in, bf16 hi/lo out)
    {
        dim3 grid(T_ / 128, H_, B_);
        attn_mma<<<grid, 256, A_TOTAL>>>(qkvh, qkvl, yh, yl);
    }
    // 3) out = y @ w_out^T -> fp32
    {
        dim3 grid(C_ / 128, M / 128);
        gemm_bf16x3<false><<<grid, 256, G_TOTAL>>>(yh, yl, woh, wol,
                                                   out, nullptr, nullptr, C_, C_);
    }
}

// round 12
// speedup vs baseline: 4.7161x; 1.0025x over previous
#include <cuda_runtime.h>
#include <cuda_bf16.h>
#include <cstdint>
#include <math.h>

#define B_ 4
#define T_ 2048
#define C_ 1024
#define H_ 16
#define D_ 64

// ---------------------------------------------------------------------------
// Scratch (allocation-free rule: __device__ globals)
// ---------------------------------------------------------------------------
__device__ __nv_bfloat16 g_qkvh[(size_t)B_ * T_ * 3 * C_];   // qkv hi/lo (GEMM epilogue)
__device__ __nv_bfloat16 g_qkvl[(size_t)B_ * T_ * 3 * C_];
__device__ __nv_bfloat16 g_xh[(size_t)B_ * T_ * C_];         // x hi/lo
__device__ __nv_bfloat16 g_xl[(size_t)B_ * T_ * C_];
__device__ __nv_bfloat16 g_yh[(size_t)B_ * T_ * C_];         // y hi/lo (attn output)
__device__ __nv_bfloat16 g_yl[(size_t)B_ * T_ * C_];
__device__ __nv_bfloat16 g_wqh[(size_t)3 * C_ * C_];         // w_qkv hi/lo
__device__ __nv_bfloat16 g_wql[(size_t)3 * C_ * C_];
__device__ __nv_bfloat16 g_woh[(size_t)C_ * C_];             // w_out hi/lo
__device__ __nv_bfloat16 g_wol[(size_t)C_ * C_];

// ---------------------------------------------------------------------------
// Baseline-PTX helpers (all valid on compute_103: no tcgen05)
// ---------------------------------------------------------------------------
__device__ __forceinline__ uint32_t smem_u32(const void* p) {
    uint32_t a;
    asm("{ .reg .u64 t; cvta.to.shared.u64 t, %1; cvt.u32.u64 %0, t; }" : "=r"(a) : "l"(p));
    return a;
}
__device__ __forceinline__ uint32_t swz128(uint32_t off) { return off ^ ((off >> 3) & 0x70); }

__device__ __forceinline__ void cp_async16(uint32_t dst, const void* src) {
    asm volatile("cp.async.cg.shared.global [%0], [%1], 16;" :: "r"(dst), "l"(src) : "memory");
}
#define CP_COMMIT()  asm volatile("cp.async.commit_group;" ::: "memory")
#define CP_WAIT(n)   asm volatile("cp.async.wait_group %0;" :: "n"(n) : "memory")

#define LDSM_X4(r0, r1, r2, r3, addr) \
    asm volatile("ldmatrix.sync.aligned.m8n8.x4.shared.b16 {%0,%1,%2,%3}, [%4];" \
        : "=r"(r0), "=r"(r1), "=r"(r2), "=r"(r3) : "r"(addr))

#define LDSM_X4_T(r0, r1, r2, r3, addr) \
    asm volatile("ldmatrix.sync.aligned.m8n8.x4.trans.shared.b16 {%0,%1,%2,%3}, [%4];" \
        : "=r"(r0), "=r"(r1), "=r"(r2), "=r"(r3) : "r"(addr))

#define MMA16816(d, a, b) \
    asm volatile("mma.sync.aligned.m16n8k16.row.col.f32.bf16.bf16.f32 " \
        "{%0,%1,%2,%3}, {%4,%5,%6,%7}, {%8,%9}, {%0,%1,%2,%3};" \
        : "+f"((d)[0]), "+f"((d)[1]), "+f"((d)[2]), "+f"((d)[3]) \
        : "r"((a)[0]), "r"((a)[1]), "r"((a)[2]), "r"((a)[3]), "r"((b)[0]), "r"((b)[1]))

__device__ __forceinline__ uint32_t pack_bf16x2(float lo, float hi) {
    uint32_t r;
    asm("cvt.rn.bf16x2.f32 %0, %1, %2;" : "=r"(r) : "f"(hi), "f"(lo));
    return r;
}
__device__ __forceinline__ float bf16lo_f(uint32_t p) { return __uint_as_float(p << 16); }
__device__ __forceinline__ float bf16hi_f(uint32_t p) { return __uint_as_float(p & 0xffff0000u); }

// ---------------------------------------------------------------------------
// hi/lo bf16 split of fp32 inputs
// ---------------------------------------------------------------------------
__global__ __launch_bounds__(256) void split_kernel(
    const float* __restrict__ src, __nv_bfloat16* __restrict__ h,
    __nv_bfloat16* __restrict__ l, int n4)
{
    int i = blockIdx.x * 256 + threadIdx.x;
    if (i >= n4) return;
    float4 v = ((const float4*)src)[i];
    uint32_t h01 = pack_bf16x2(v.x, v.y), h23 = pack_bf16x2(v.z, v.w);
    uint32_t l01 = pack_bf16x2(v.x - bf16lo_f(h01), v.y - bf16hi_f(h01));
    uint32_t l23 = pack_bf16x2(v.z - bf16lo_f(h23), v.w - bf16hi_f(h23));
    uint32_t* hp = (uint32_t*)(h + 4 * (size_t)i);
    uint32_t* lp = (uint32_t*)(l + 4 * (size_t)i);
    hp[0] = h01; hp[1] = h23;
    lp[0] = l01; lp[1] = l23;
}

// ---------------------------------------------------------------------------
// cp.async 3-stage mma.sync bf16x3 GEMM with register-fragment double
// buffering (prefetch ks+1 frags during ks MMAs):
// OUT[m,n] = sum_k A[m,k]*B[n,k];  D = Ah*Bh + Ah*Bl + Al*Bh
// ---------------------------------------------------------------------------
#define G_STAGE 65536
#define G_AH 0
#define G_AL 16384
#define G_BH 32768
#define G_BL 49152
#define G_TOTAL (3 * G_STAGE)

#define G_LOAD_A(bf, ks, mt) do { \
    uint32_t bo_ = swz128((uint32_t)((wm * 32 + (mt) * 16 + a_r) * 128 + ((ks) * 16 + a_k) * 2)); \
    LDSM_X4(fAh[bf][mt][0], fAh[bf][mt][1], fAh[bf][mt][2], fAh[bf][mt][3], s0 + G_AH + bo_); \
    LDSM_X4(fAl[bf][mt][0], fAl[bf][mt][1], fAl[bf][mt][2], fAl[bf][mt][3], s0 + G_AL + bo_); \
} while (0)

#define G_LOAD_B(bf, ks, p) do { \
    uint32_t bo_ = swz128((uint32_t)((wn * 64 + (p) * 16 + b_n) * 128 + ((ks) * 16 + b_k) * 2)); \
    uint32_t r0_, r1_, r2_, r3_; \
    LDSM_X4(r0_, r1_, r2_, r3_, s0 + G_BH + bo_); \
    fBh[bf][(p)*2][0] = r0_; fBh[bf][(p)*2][1] = r1_; \
    fBh[bf][(p)*2+1][0] = r2_; fBh[bf][(p)*2+1][1] = r3_; \
    LDSM_X4(r0_, r1_, r2_, r3_, s0 + G_BL + bo_); \
    fBl[bf][(p)*2][0] = r0_; fBl[bf][(p)*2][1] = r1_; \
    fBl[bf][(p)*2+1][0] = r2_; fBl[bf][(p)*2+1][1] = r3_; \
} while (0)

#define G_LOAD_FRAGS(bf, ks) do { \
    G_LOAD_A(bf, ks, 0); G_LOAD_A(bf, ks, 1); \
    G_LOAD_B(bf, ks, 0); G_LOAD_B(bf, ks, 1); G_LOAD_B(bf, ks, 2); G_LOAD_B(bf, ks, 3); \
} while (0)

template <bool BF16OUT>
__global__ __launch_bounds__(256, 1) void gemm_bf16x3(
    const __nv_bfloat16* __restrict__ Ah, const __nv_bfloat16* __restrict__ Al,
    const __nv_bfloat16* __restrict__ Bh, const __nv_bfloat16* __restrict__ Bl,
    float* __restrict__ OUT,
    __nv_bfloat16* __restrict__ OUTH, __nv_bfloat16* __restrict__ OUTL,
    int N, int K)
{
    extern __shared__ char smem[];
    const uint32_t sb = smem_u32(smem);
    const int tid  = threadIdx.x;
    const int lane = tid & 31;
    const int warp = tid >> 5;
    const int wm   = warp >> 1;
    const int wn   = warp & 1;

    const size_t arow0 = (size_t)blockIdx.y * 128;
    const size_t brow0 = (size_t)blockIdx.x * 128;
    const __nv_bfloat16* pAh = Ah + arow0 * K;
    const __nv_bfloat16* pAl = Al + arow0 * K;
    const __nv_bfloat16* pBh = Bh + brow0 * K;
    const __nv_bfloat16* pBl = Bl + brow0 * K;

    const int nchunks = K >> 6;

    auto issue = [&](int ch) {
        const int k0 = ch << 6;
        const uint32_t s0 = sb + (ch % 3) * G_STAGE;
#pragma unroll
        for (int i = 0; i < 4; i++) {
            int ci = tid + i * 256;
            int r = ci >> 3, c = ci & 7;
            uint32_t so = swz128((uint32_t)(r * 128 + c * 16));
            size_t go = (size_t)r * K + k0 + c * 8;
            cp_async16(s0 + G_AH + so, pAh + go);
            cp_async16(s0 + G_AL + so, pAl + go);
            cp_async16(s0 + G_BH + so, pBh + go);
            cp_async16(s0 + G_BL + so, pBl + go);
        }
        CP_COMMIT();
    };

    float acc[2][8][4];
#pragma unroll
    for (int mt = 0; mt < 2; mt++)
#pragma unroll
        for (int nt = 0; nt < 8; nt++)
#pragma unroll
            for (int r = 0; r < 4; r++) acc[mt][nt][r] = 0.f;

    const int a_r  = lane & 15;
    const int a_k  = (lane >> 4) * 8;
    const int b_rr = lane & 7;
    const int b_g  = lane >> 3;
    const int b_n  = ((b_g >> 1) * 8) + b_rr;
    const int b_k  = (b_g & 1) * 8;

    uint32_t fAh[2][2][4], fAl[2][2][4];   // [buf][mtile][reg]
    uint32_t fBh[2][8][2], fBl[2][8][2];   // [buf][ntile][reg]

    issue(0);
    issue(1);                          // nchunks >= 2 always (K >= 128)

    for (int ch = 0; ch < nchunks; ch++) {
        if (ch + 1 < nchunks) CP_WAIT(1); else CP_WAIT(0);
        __syncthreads();               // stage ch published
        if (ch + 2 < nchunks) issue(ch + 2);

        const uint32_t s0 = sb + (ch % 3) * G_STAGE;
        G_LOAD_FRAGS(0, 0);            // exposed once per chunk
#pragma unroll
        for (int ks = 0; ks < 4; ks++) {
            if (ks < 3) G_LOAD_FRAGS((ks + 1) & 1, ks + 1);   // overlap with MMAs
            const int bf = ks & 1;
#pragma unroll
            for (int mt = 0; mt < 2; mt++)
#pragma unroll
                for (int nt = 0; nt < 8; nt++) MMA16816(acc[mt][nt], fAh[bf][mt], fBh[bf][nt]);
#pragma unroll
            for (int mt = 0; mt < 2; mt++)
#pragma unroll
                for (int nt = 0; nt < 8; nt++) MMA16816(acc[mt][nt], fAh[bf][mt], fBl[bf][nt]);
#pragma unroll
            for (int mt = 0; mt < 2; mt++)
#pragma unroll
                for (int nt = 0; nt < 8; nt++) MMA16816(acc[mt][nt], fAl[bf][mt], fBh[bf][nt]);
        }
        // no trailing barrier: next leading barrier covers stage reuse
    }

    const int c_r = lane >> 2;
    const int c_c = (lane & 3) * 2;
#pragma unroll
    for (int mt = 0; mt < 2; mt++) {
        size_t row = arow0 + wm * 32 + mt * 16 + c_r;
        size_t off0 = row * N       + brow0 + wn * 64 + c_c;
        size_t off1 = (row + 8) * N + brow0 + wn * 64 + c_c;
        if (BF16OUT) {
#pragma unroll
            for (int nt = 0; nt < 8; nt++) {
                float y0 = acc[mt][nt][0], y1 = acc[mt][nt][1];
                float y2 = acc[mt][nt][2], y3 = acc[mt][nt][3];
                uint32_t h01 = pack_bf16x2(y0, y1);
                uint32_t l01 = pack_bf16x2(y0 - bf16lo_f(h01), y1 - bf16hi_f(h01));
                uint32_t h23 = pack_bf16x2(y2, y3);
                uint32_t l23 = pack_bf16x2(y2 - bf16lo_f(h23), y3 - bf16hi_f(h23));
                *(uint32_t*)(OUTH + off0 + nt * 8) = h01;
                *(uint32_t*)(OUTL + off0 + nt * 8) = l01;
                *(uint32_t*)(OUTH + off1 + nt * 8) = h23;
                *(uint32_t*)(OUTL + off1 + nt * 8) = l23;
            }
        } else {
#pragma unroll
            for (int nt = 0; nt < 8; nt++) {
                *(float2*)(OUT + off0 + nt * 8) = make_float2(acc[mt][nt][0], acc[mt][nt][1]);
                *(float2*)(OUT + off1 + nt * 8) = make_float2(acc[mt][nt][2], acc[mt][nt][3]);
            }
        }
    }
}

// ---------------------------------------------------------------------------
// Tensor-core causal flash attention, bf16 hi/lo qkv input.
// 3-stage cp.async K/V pipeline; register-fragment double buffering in both
// the QK and PV MMA loops (flattened, fully unrolled).
// ---------------------------------------------------------------------------
#define AQ_H 0
#define AQ_L 16384
#define A_STG 32768          // stage base; per stage: KH 0, KL 8K, VH 16K, VL 24K
#define A_SSZ 32768
#define A_TOTAL (A_STG + 3 * A_SSZ)

#define A_LOAD_KFRAG(bf, ks, p) do { \
    uint32_t bo_ = swz128((uint32_t)(((p) * 16 + b_row) * 128 + ((ks) * 16 + b_k) * 2)); \
    LDSM_X4(kfh[bf][0][0], kfh[bf][0][1], kfh[bf][1][0], kfh[bf][1][1], sK + bo_); \
    LDSM_X4(kfl[bf][0][0], kfl[bf][0][1], kfl[bf][1][0], kfl[bf][1][1], sK + 8192 + bo_); \
} while (0)

#define A_LOAD_VFRAG(bf, ks, p) do { \
    uint32_t bo_ = swz128((uint32_t)(((ks) * 16 + (b_g & 1) * 8 + b_rr) * 128 + \
                                     ((p) * 16 + (b_g >> 1) * 8) * 2)); \
    LDSM_X4_T(vfh[bf][0][0], vfh[bf][0][1], vfh[bf][1][0], vfh[bf][1][1], sV + bo_); \
    LDSM_X4_T(vfl[bf][0][0], vfl[bf][0][1], vfl[bf][1][0], vfl[bf][1][1], sV + 8192 + bo_); \
} while (0)

__global__ __launch_bounds__(256, 1) void attn_mma(
    const __nv_bfloat16* __restrict__ qkvh, const __nv_bfloat16* __restrict__ qkvl,
    __nv_bfloat16* __restrict__ yh, __nv_bfloat16* __restrict__ yl)
{
    extern __shared__ char smem[];
    const uint32_t sb = smem_u32(smem);
    const int qt   = blockIdx.x;
    const int h    = blockIdx.y;
    const int b    = blockIdx.z;
    const int tid  = threadIdx.x;
    const int lane = tid & 31;
    const int warp = tid >> 5;

    const size_t rs = (size_t)3 * C_;
    const __nv_bfloat16* Qh = qkvh + ((size_t)(b * T_ + qt * 128)) * rs + h * D_;
    const __nv_bfloat16* Ql = qkvl + ((size_t)(b * T_ + qt * 128)) * rs + h * D_;
    const __nv_bfloat16* Kh = qkvh + ((size_t)b * T_) * rs + C_     + h * D_;
    const __nv_bfloat16* Kl = qkvl + ((size_t)b * T_) * rs + C_     + h * D_;
    const __nv_bfloat16* Vh = qkvh + ((size_t)b * T_) * rs + 2 * C_ + h * D_;
    const __nv_bfloat16* Vl = qkvl + ((size_t)b * T_) * rs + 2 * C_ + h * D_;

    // ---- Q tile loads ----
#pragma unroll
    for (int i = 0; i < 4; i++) {
        int lin = i * 256 + tid;
        int r = lin >> 3, c = lin & 7;
        uint32_t so = swz128((uint32_t)(r * 128 + c * 16));
        cp_async16(sb + AQ_H + so, Qh + (size_t)r * rs + c * 8);
        cp_async16(sb + AQ_L + so, Ql + (size_t)r * rs + c * 8);
    }
    CP_COMMIT();

    auto issue_blk = [&](int kb) {
        const uint32_t s0 = sb + A_STG + (kb % 3) * A_SSZ;
        const size_t g0 = (size_t)(kb * 64) * rs;
#pragma unroll
        for (int i = 0; i < 2; i++) {
            int lin = i * 256 + tid;
            int r = lin >> 3, c = lin & 7;
            uint32_t so = swz128((uint32_t)(r * 128 + c * 16));
            size_t go = g0 + (size_t)r * rs + c * 8;
            cp_async16(s0 + 0     + so, Kh + go);
            cp_async16(s0 + 8192  + so, Kl + go);
            cp_async16(s0 + 16384 + so, Vh + go);
            cp_async16(s0 + 24576 + so, Vl + go);
        }
        CP_COMMIT();
    };

    const int nb = 2 * (qt + 1);       // >= 2 always
    issue_blk(0);
    CP_WAIT(1);                        // Q done (blk0 may be in flight)
    __syncthreads();

    // ---- Q fragments (resident) ----
    const int a_r = lane & 15, a_k = (lane >> 4) * 8;
    uint32_t fQh[4][4], fQl[4][4];
#pragma unroll
    for (int ks = 0; ks < 4; ks++) {
        uint32_t bo = swz128((uint32_t)((warp * 16 + a_r) * 128 + (ks * 16 + a_k) * 2));
        LDSM_X4(fQh[ks][0], fQh[ks][1], fQh[ks][2], fQh[ks][3], sb + AQ_H + bo);
        LDSM_X4(fQl[ks][0], fQl[ks][1], fQl[ks][2], fQl[ks][3], sb + AQ_L + bo);
    }
    issue_blk(1);

    float oacc[8][4];
#pragma unroll
    for (int j = 0; j < 8; j++)
#pragma unroll
        for (int r = 0; r < 4; r++) oacc[j][r] = 0.f;
    float mrow[2] = {-1e30f, -1e30f};
    float lrow[2] = {0.f, 0.f};

    const int b_rr = lane & 7, b_g = lane >> 3;
    const int b_row = (b_g >> 1) * 8 + b_rr;
    const int b_k   = (b_g & 1) * 8;
    const int qg0 = qt * 128 + warp * 16 + (lane >> 2);

    uint32_t kfh[2][2][2], kfl[2][2][2];   // [buf][tile][reg]
    uint32_t vfh[2][2][2], vfl[2][2][2];

    for (int kb = 0; kb < nb; kb++) {
        if (kb + 1 < nb) CP_WAIT(1); else CP_WAIT(0);
        __syncthreads();               // stage kb published
        if (kb + 2 < nb) issue_blk(kb + 2);

        const uint32_t sK = sb + A_STG + (kb % 3) * A_SSZ;
        const uint32_t sV = sK + 16384;

        // ---- S = Q K^T (bf16x3), frag-pipelined ----
        float sacc[8][4];
#pragma unroll
        for (int j = 0; j < 8; j++)
#pragma unroll
            for (int r = 0; r < 4; r++) sacc[j][r] = 0.f;

        A_LOAD_KFRAG(0, 0, 0);
#pragma unroll
        for (int it = 0; it < 16; it++) {
            const int ks = it >> 2, p = it & 3;
            if (it < 15) A_LOAD_KFRAG((it + 1) & 1, (it + 1) >> 2, (it + 1) & 3);
            const int bf = it & 1;
            MMA16816(sacc[2*p],   fQh[ks], kfh[bf][0]);
            MMA16816(sacc[2*p+1], fQh[ks], kfh[bf][1]);
            MMA16816(sacc[2*p],   fQh[ks], kfl[bf][0]);
            MMA16816(sacc[2*p+1], fQh[ks], kfl[bf][1]);
            MMA16816(sacc[2*p],   fQl[ks], kfh[bf][0]);
            MMA16816(sacc[2*p+1], fQl[ks], kfh[bf][1]);
        }

        // prefetch first V frags; latency hides under softmax
        A_LOAD_VFRAG(0, 0, 0);

        // ---- scale + causal mask ----
#pragma unroll
        for (int j = 0; j < 8; j++)
#pragma unroll
            for (int r = 0; r < 4; r++) sacc[j][r] *= 0.125f;
        if (kb >= 2 * qt) {
            const int kbase = kb * 64 + (lane & 3) * 2;
#pragma unroll
            for (int j = 0; j < 8; j++) {
#pragma unroll
                for (int cc = 0; cc < 2; cc++) {
                    int kg = kbase + j * 8 + cc;
                    if (kg > qg0)     sacc[j][cc]     = -1e30f;
                    if (kg > qg0 + 8) sacc[j][2 + cc] = -1e30f;
                }
            }
        }

        // ---- online softmax ----
        float m0 = mrow[0], m1 = mrow[1];
#pragma unroll
        for (int j = 0; j < 8; j++) {
            m0 = fmaxf(m0, fmaxf(sacc[j][0], sacc[j][1]));
            m1 = fmaxf(m1, fmaxf(sacc[j][2], sacc[j][3]));
        }
        m0 = fmaxf(m0, __shfl_xor_sync(0xffffffffu, m0, 1));
        m0 = fmaxf(m0, __shfl_xor_sync(0xffffffffu, m0, 2));
        m1 = fmaxf(m1, __shfl_xor_sync(0xffffffffu, m1, 1));
        m1 = fmaxf(m1, __shfl_xor_sync(0xffffffffu, m1, 2));
        const float f0 = __expf(mrow[0] - m0), f1 = __expf(mrow[1] - m1);
        mrow[0] = m0; mrow[1] = m1;
        lrow[0] *= f0; lrow[1] *= f1;
#pragma unroll
        for (int j = 0; j < 8; j++) {
            oacc[j][0] *= f0; oacc[j][1] *= f0;
            oacc[j][2] *= f1; oacc[j][3] *= f1;
        }

        uint32_t ah[4][4], al[4][4];
#pragma unroll
        for (int j = 0; j < 8; j++) {
            float p0 = __expf(sacc[j][0] - m0);
            float p1 = __expf(sacc[j][1] - m0);
            float p2 = __expf(sacc[j][2] - m1);
            float p3 = __expf(sacc[j][3] - m1);
            lrow[0] += p0 + p1;
            lrow[1] += p2 + p3;
            uint32_t ph01 = pack_bf16x2(p0, p1);
            uint32_t ph23 = pack_bf16x2(p2, p3);
            uint32_t pl01 = pack_bf16x2(p0 - bf16lo_f(ph01), p1 - bf16hi_f(ph01));
            uint32_t pl23 = pack_bf16x2(p2 - bf16lo_f(ph23), p3 - bf16hi_f(ph23));
            const int ks = j >> 1, sl = (j & 1) * 2;
            ah[ks][sl]     = ph01;  ah[ks][sl + 1] = ph23;
            al[ks][sl]     = pl01;  al[ks][sl + 1] = pl23;
        }

        // ---- O += P V (bf16x3), frag-pipelined ----
#pragma unroll
        for (int it = 0; it < 16; it++) {
            const int ks = it >> 2, p = it & 3;
            if (it < 15) A_LOAD_VFRAG((it + 1) & 1, (it + 1) >> 2, (it + 1) & 3);
            const int bf = it & 1;
            MMA16816(oacc[2*p],   ah[ks], vfh[bf][0]);
            MMA16816(oacc[2*p+1], ah[ks], vfh[bf][1]);
            MMA16816(oacc[2*p],   ah[ks], vfl[bf][0]);
            MMA16816(oacc[2*p+1], ah[ks], vfl[bf][1]);
            MMA16816(oacc[2*p],   al[ks], vfh[bf][0]);
            MMA16816(oacc[2*p+1], al[ks], vfh[bf][1]);
        }
        // no trailing barrier (3-stage ring)
    }

    // ---- finalize ----
    lrow[0] += __shfl_xor_sync(0xffffffffu, lrow[0], 1);
    lrow[0] += __shfl_xor_sync(0xffffffffu, lrow[0], 2);
    lrow[1] += __shfl_xor_sync(0xffffffffu, lrow[1], 1);
    lrow[1] += __shfl_xor_sync(0xffffffffu, lrow[1], 2);
    const float inv0 = 1.f / lrow[0], inv1 = 1.f / lrow[1];

    const int t0 = qt * 128 + warp * 16 + (lane >> 2);
    const size_t base0 = ((size_t)(b * T_ + t0)) * C_ + h * D_ + (lane & 3) * 2;
    const size_t base1 = base0 + 8 * (size_t)C_;
#pragma unroll
    for (int j = 0; j < 8; j++) {
        float y0 = oacc[j][0] * inv0, y1 = oacc[j][1] * inv0;
        float y2 = oacc[j][2] * inv1, y3 = oacc[j][3] * inv1;
        uint32_t h01 = pack_bf16x2(y0, y1);
        uint32_t l01 = pack_bf16x2(y0 - bf16lo_f(h01), y1 - bf16hi_f(h01));
        uint32_t h23 = pack_bf16x2(y2, y3);
        uint32_t l23 = pack_bf16x2(y2 - bf16lo_f(h23), y3 - bf16hi_f(h23));
        *(uint32_t*)(yh + base0 + j * 8) = h01;
        *(uint32_t*)(yl + base0 + j * 8) = l01;
        *(uint32_t*)(yh + base1 + j * 8) = h23;
        *(uint32_t*)(yl + base1 + j * 8) = l23;
    }
}

// ---------------------------------------------------------------------------
extern "C" void kernel_launch(void* const* d_in, const int* in_sizes, int n_in,
                              void* d_out, int out_size)
{
    const float* x     = (const float*)d_in[0];   // [B,T,C]
    const float* w_qkv = (const float*)d_in[1];   // [3C,C]
    const float* w_out = (const float*)d_in[2];   // [C,C]
    float* out = (float*)d_out;                   // [B,T,C]

    __nv_bfloat16 *qkvh, *qkvl, *xh, *xl, *yh, *yl, *wqh, *wql, *woh, *wol;
    cudaGetSymbolAddress((void**)&qkvh, g_qkvh); cudaGetSymbolAddress((void**)&qkvl, g_qkvl);
    cudaGetSymbolAddress((void**)&xh,  g_xh);  cudaGetSymbolAddress((void**)&xl,  g_xl);
    cudaGetSymbolAddress((void**)&yh,  g_yh);  cudaGetSymbolAddress((void**)&yl,  g_yl);
    cudaGetSymbolAddress((void**)&wqh, g_wqh); cudaGetSymbolAddress((void**)&wql, g_wql);
    cudaGetSymbolAddress((void**)&woh, g_woh); cudaGetSymbolAddress((void**)&wol, g_wol);

    cudaFuncSetAttribute(gemm_bf16x3<true>,  cudaFuncAttributeMaxDynamicSharedMemorySize, G_TOTAL);
    cudaFuncSetAttribute(gemm_bf16x3<false>, cudaFuncAttributeMaxDynamicSharedMemorySize, G_TOTAL);
    cudaFuncSetAttribute(attn_mma,           cudaFuncAttributeMaxDynamicSharedMemorySize, A_TOTAL);

    const int M = B_ * T_;                  // 8192
    const int n_x  = M * C_;
    const int n_wq = 3 * C_ * C_;
    const int n_wo = C_ * C_;

    split_kernel<<<(n_x / 4 + 255) / 256, 256>>>(x, xh, xl, n_x / 4);
    split_kernel<<<(n_wq / 4 + 255) / 256, 256>>>(w_qkv, wqh, wql, n_wq / 4);
    split_kernel<<<(n_wo / 4 + 255) / 256, 256>>>(w_out, woh, wol, n_wo / 4);

    // 1) qkv = x @ w_qkv^T -> bf16 hi/lo directly
    {
        dim3 grid(3 * C_ / 128, M / 128);
        gemm_bf16x3<true><<<grid, 256, G_TOTAL>>>(xh, xl, wqh, wql,
                                                  nullptr, qkvh, qkvl, 3 * C_, C_);
    }
    // 2) causal attention (bf16 in, bf16 hi/lo out)
    {
        dim3 grid(T_ / 128, H_, B_);
        attn_mma<<<grid, 256, A_TOTAL>>>(qkvh, qkvl, yh, yl);
    }
    // 3) out = y @ w_out^T -> fp32
    {
        dim3 grid(C_ / 128, M / 128);
        gemm_bf16x3<false><<<grid, 256, G_TOTAL>>>(yh, yl, woh, wol,
                                                   out, nullptr, nullptr, C_, C_);
    }
}

// round 13
// speedup vs baseline: 5.1430x; 1.0905x over previous
#include <cuda_runtime.h>
#include <cuda_bf16.h>
#include <cstdint>
#include <math.h>

#define B_ 4
#define T_ 2048
#define C_ 1024
#define H_ 16
#define D_ 64

// ---------------------------------------------------------------------------
// Scratch (allocation-free rule: __device__ globals)
// ---------------------------------------------------------------------------
__device__ __nv_bfloat16 g_qkvh[(size_t)B_ * T_ * 3 * C_];   // qkv hi/lo (GEMM epilogue)
__device__ __nv_bfloat16 g_qkvl[(size_t)B_ * T_ * 3 * C_];
__device__ __nv_bfloat16 g_xh[(size_t)B_ * T_ * C_];         // x hi/lo
__device__ __nv_bfloat16 g_xl[(size_t)B_ * T_ * C_];
__device__ __nv_bfloat16 g_yh[(size_t)B_ * T_ * C_];         // y hi/lo (attn output)
__device__ __nv_bfloat16 g_yl[(size_t)B_ * T_ * C_];
__device__ __nv_bfloat16 g_wqh[(size_t)3 * C_ * C_];         // w_qkv hi/lo
__device__ __nv_bfloat16 g_wql[(size_t)3 * C_ * C_];
__device__ __nv_bfloat16 g_woh[(size_t)C_ * C_];             // w_out hi/lo
__device__ __nv_bfloat16 g_wol[(size_t)C_ * C_];

// ---------------------------------------------------------------------------
// Baseline-PTX helpers (all valid on compute_103: no tcgen05)
// ---------------------------------------------------------------------------
__device__ __forceinline__ uint32_t smem_u32(const void* p) {
    uint32_t a;
    asm("{ .reg .u64 t; cvta.to.shared.u64 t, %1; cvt.u32.u64 %0, t; }" : "=r"(a) : "l"(p));
    return a;
}
__device__ __forceinline__ uint32_t swz128(uint32_t off) { return off ^ ((off >> 3) & 0x70); }

__device__ __forceinline__ void cp_async16(uint32_t dst, const void* src) {
    asm volatile("cp.async.cg.shared.global [%0], [%1], 16;" :: "r"(dst), "l"(src) : "memory");
}
#define CP_COMMIT()  asm volatile("cp.async.commit_group;" ::: "memory")
#define CP_WAIT(n)   asm volatile("cp.async.wait_group %0;" :: "n"(n) : "memory")

#define LDSM_X4(r0, r1, r2, r3, addr) \
    asm volatile("ldmatrix.sync.aligned.m8n8.x4.shared.b16 {%0,%1,%2,%3}, [%4];" \
        : "=r"(r0), "=r"(r1), "=r"(r2), "=r"(r3) : "r"(addr))

#define LDSM_X4_T(r0, r1, r2, r3, addr) \
    asm volatile("ldmatrix.sync.aligned.m8n8.x4.trans.shared.b16 {%0,%1,%2,%3}, [%4];" \
        : "=r"(r0), "=r"(r1), "=r"(r2), "=r"(r3) : "r"(addr))

#define MMA16816(d, a, b) \
    asm volatile("mma.sync.aligned.m16n8k16.row.col.f32.bf16.bf16.f32 " \
        "{%0,%1,%2,%3}, {%4,%5,%6,%7}, {%8,%9}, {%0,%1,%2,%3};" \
        : "+f"((d)[0]), "+f"((d)[1]), "+f"((d)[2]), "+f"((d)[3]) \
        : "r"((a)[0]), "r"((a)[1]), "r"((a)[2]), "r"((a)[3]), "r"((b)[0]), "r"((b)[1]))

__device__ __forceinline__ uint32_t pack_bf16x2(float lo, float hi) {
    uint32_t r;
    asm("cvt.rn.bf16x2.f32 %0, %1, %2;" : "=r"(r) : "f"(hi), "f"(lo));
    return r;
}
__device__ __forceinline__ float bf16lo_f(uint32_t p) { return __uint_as_float(p << 16); }
__device__ __forceinline__ float bf16hi_f(uint32_t p) { return __uint_as_float(p & 0xffff0000u); }

// ---------------------------------------------------------------------------
// hi/lo bf16 split of fp32 inputs
// ---------------------------------------------------------------------------
__global__ __launch_bounds__(256) void split_kernel(
    const float* __restrict__ src, __nv_bfloat16* __restrict__ h,
    __nv_bfloat16* __restrict__ l, int n4)
{
    int i = blockIdx.x * 256 + threadIdx.x;
    if (i >= n4) return;
    float4 v = ((const float4*)src)[i];
    uint32_t h01 = pack_bf16x2(v.x, v.y), h23 = pack_bf16x2(v.z, v.w);
    uint32_t l01 = pack_bf16x2(v.x - bf16lo_f(h01), v.y - bf16hi_f(h01));
    uint32_t l23 = pack_bf16x2(v.z - bf16lo_f(h23), v.w - bf16hi_f(h23));
    uint32_t* hp = (uint32_t*)(h + 4 * (size_t)i);
    uint32_t* lp = (uint32_t*)(l + 4 * (size_t)i);
    hp[0] = h01; hp[1] = h23;
    lp[0] = l01; lp[1] = l23;
}

// ---------------------------------------------------------------------------
// mma.sync bf16x3 GEMM, 2 CTAs/SM (4 warps/SMSP):
// CTA tile 128(M) x 64(N), warp tile 32x32, BK=64, 2-stage cp.async.
// OUT[m,n] = sum_k A[m,k]*B[n,k];  D = Ah*Bh + Ah*Bl + Al*Bh
// smem/stage: AH 16K | AL 16K | BH 8K | BL 8K = 48KB; 2 stages = 96KB/CTA.
// ---------------------------------------------------------------------------
#define G_STAGE 49152
#define G_AH 0
#define G_AL 16384
#define G_BH 32768
#define G_BL 40960
#define G_TOTAL (2 * G_STAGE)

template <bool BF16OUT>
__global__ __launch_bounds__(256, 2) void gemm_bf16x3(
    const __nv_bfloat16* __restrict__ Ah, const __nv_bfloat16* __restrict__ Al,
    const __nv_bfloat16* __restrict__ Bh, const __nv_bfloat16* __restrict__ Bl,
    float* __restrict__ OUT,
    __nv_bfloat16* __restrict__ OUTH, __nv_bfloat16* __restrict__ OUTL,
    int N, int K)
{
    extern __shared__ char smem[];
    const uint32_t sb = smem_u32(smem);
    const int tid  = threadIdx.x;
    const int lane = tid & 31;
    const int warp = tid >> 5;
    const int wm   = warp >> 1;      // 0..3 : 32-row slice
    const int wn   = warp & 1;       // 0..1 : 32-col slice

    const size_t arow0 = (size_t)blockIdx.y * 128;
    const size_t brow0 = (size_t)blockIdx.x * 64;
    const __nv_bfloat16* pAh = Ah + arow0 * K;
    const __nv_bfloat16* pAl = Al + arow0 * K;
    const __nv_bfloat16* pBh = Bh + brow0 * K;
    const __nv_bfloat16* pBl = Bl + brow0 * K;

    const int nchunks = K >> 6;

    auto issue = [&](int ch) {
        const int k0 = ch << 6;
        const uint32_t s0 = sb + (ch & 1) * G_STAGE;
#pragma unroll
        for (int i = 0; i < 4; i++) {            // A: 128 rows x 8 chunks
            int ci = tid + i * 256;
            int r = ci >> 3, c = ci & 7;
            uint32_t so = swz128((uint32_t)(r * 128 + c * 16));
            size_t go = (size_t)r * K + k0 + c * 8;
            cp_async16(s0 + G_AH + so, pAh + go);
            cp_async16(s0 + G_AL + so, pAl + go);
        }
#pragma unroll
        for (int i = 0; i < 2; i++) {            // B: 64 rows x 8 chunks
            int ci = tid + i * 256;
            int r = ci >> 3, c = ci & 7;
            uint32_t so = swz128((uint32_t)(r * 128 + c * 16));
            size_t go = (size_t)r * K + k0 + c * 8;
            cp_async16(s0 + G_BH + so, pBh + go);
            cp_async16(s0 + G_BL + so, pBl + go);
        }
        CP_COMMIT();
    };

    float acc[2][4][4];
#pragma unroll
    for (int mt = 0; mt < 2; mt++)
#pragma unroll
        for (int nt = 0; nt < 4; nt++)
#pragma unroll
            for (int r = 0; r < 4; r++) acc[mt][nt][r] = 0.f;

    const int a_r  = lane & 15;
    const int a_k  = (lane >> 4) * 8;
    const int b_rr = lane & 7;
    const int b_g  = lane >> 3;
    const int b_n  = ((b_g >> 1) * 8) + b_rr;
    const int b_k  = (b_g & 1) * 8;

    issue(0);

    for (int ch = 0; ch < nchunks; ch++) {
        if (ch + 1 < nchunks) { issue(ch + 1); CP_WAIT(1); }
        else                  { CP_WAIT(0); }
        __syncthreads();

        const uint32_t s0 = sb + (ch & 1) * G_STAGE;
#pragma unroll
        for (int ks = 0; ks < 4; ks++) {
            const int kk = ks * 16;
            uint32_t fAh[2][4], fAl[2][4];
#pragma unroll
            for (int mt = 0; mt < 2; mt++) {
                uint32_t bo = swz128((uint32_t)((wm * 32 + mt * 16 + a_r) * 128 + (kk + a_k) * 2));
                LDSM_X4(fAh[mt][0], fAh[mt][1], fAh[mt][2], fAh[mt][3], s0 + G_AH + bo);
                LDSM_X4(fAl[mt][0], fAl[mt][1], fAl[mt][2], fAl[mt][3], s0 + G_AL + bo);
            }
            uint32_t fBh[4][2], fBl[4][2];
#pragma unroll
            for (int p = 0; p < 2; p++) {
                uint32_t bo = swz128((uint32_t)((wn * 32 + p * 16 + b_n) * 128 + (kk + b_k) * 2));
                uint32_t r0, r1, r2, r3;
                LDSM_X4(r0, r1, r2, r3, s0 + G_BH + bo);
                fBh[p*2][0] = r0; fBh[p*2][1] = r1; fBh[p*2+1][0] = r2; fBh[p*2+1][1] = r3;
                LDSM_X4(r0, r1, r2, r3, s0 + G_BL + bo);
                fBl[p*2][0] = r0; fBl[p*2][1] = r1; fBl[p*2+1][0] = r2; fBl[p*2+1][1] = r3;
            }
#pragma unroll
            for (int mt = 0; mt < 2; mt++)
#pragma unroll
                for (int nt = 0; nt < 4; nt++) MMA16816(acc[mt][nt], fAh[mt], fBh[nt]);
#pragma unroll
            for (int mt = 0; mt < 2; mt++)
#pragma unroll
                for (int nt = 0; nt < 4; nt++) MMA16816(acc[mt][nt], fAh[mt], fBl[nt]);
#pragma unroll
            for (int mt = 0; mt < 2; mt++)
#pragma unroll
                for (int nt = 0; nt < 4; nt++) MMA16816(acc[mt][nt], fAl[mt], fBh[nt]);
        }
        __syncthreads();
    }

    const int c_r = lane >> 2;
    const int c_c = (lane & 3) * 2;
#pragma unroll
    for (int mt = 0; mt < 2; mt++) {
        size_t row = arow0 + wm * 32 + mt * 16 + c_r;
        size_t off0 = row * N       + brow0 + wn * 32 + c_c;
        size_t off1 = (row + 8) * N + brow0 + wn * 32 + c_c;
        if (BF16OUT) {
#pragma unroll
            for (int nt = 0; nt < 4; nt++) {
                float y0 = acc[mt][nt][0], y1 = acc[mt][nt][1];
                float y2 = acc[mt][nt][2], y3 = acc[mt][nt][3];
                uint32_t h01 = pack_bf16x2(y0, y1);
                uint32_t l01 = pack_bf16x2(y0 - bf16lo_f(h01), y1 - bf16hi_f(h01));
                uint32_t h23 = pack_bf16x2(y2, y3);
                uint32_t l23 = pack_bf16x2(y2 - bf16lo_f(h23), y3 - bf16hi_f(h23));
                *(uint32_t*)(OUTH + off0 + nt * 8) = h01;
                *(uint32_t*)(OUTL + off0 + nt * 8) = l01;
                *(uint32_t*)(OUTH + off1 + nt * 8) = h23;
                *(uint32_t*)(OUTL + off1 + nt * 8) = l23;
            }
        } else {
#pragma unroll
            for (int nt = 0; nt < 4; nt++) {
                *(float2*)(OUT + off0 + nt * 8) = make_float2(acc[mt][nt][0], acc[mt][nt][1]);
                *(float2*)(OUT + off1 + nt * 8) = make_float2(acc[mt][nt][2], acc[mt][nt][3]);
            }
        }
    }
}

// ---------------------------------------------------------------------------
// Tensor-core causal flash attention, bf16 hi/lo qkv input (unchanged R12).
// 3-stage cp.async K/V pipeline.
// ---------------------------------------------------------------------------
#define AQ_H 0
#define AQ_L 16384
#define A_STG 32768          // stage base; per stage: KH 0, KL 8K, VH 16K, VL 24K
#define A_SSZ 32768
#define A_TOTAL (A_STG + 3 * A_SSZ)

#define A_LOAD_KFRAG(bf, ks, p) do { \
    uint32_t bo_ = swz128((uint32_t)(((p) * 16 + b_row) * 128 + ((ks) * 16 + b_k) * 2)); \
    LDSM_X4(kfh[bf][0][0], kfh[bf][0][1], kfh[bf][1][0], kfh[bf][1][1], sK + bo_); \
    LDSM_X4(kfl[bf][0][0], kfl[bf][0][1], kfl[bf][1][0], kfl[bf][1][1], sK + 8192 + bo_); \
} while (0)

#define A_LOAD_VFRAG(bf, ks, p) do { \
    uint32_t bo_ = swz128((uint32_t)(((ks) * 16 + (b_g & 1) * 8 + b_rr) * 128 + \
                                     ((p) * 16 + (b_g >> 1) * 8) * 2)); \
    LDSM_X4_T(vfh[bf][0][0], vfh[bf][0][1], vfh[bf][1][0], vfh[bf][1][1], sV + bo_); \
    LDSM_X4_T(vfl[bf][0][0], vfl[bf][0][1], vfl[bf][1][0], vfl[bf][1][1], sV + 8192 + bo_); \
} while (0)

__global__ __launch_bounds__(256, 1) void attn_mma(
    const __nv_bfloat16* __restrict__ qkvh, const __nv_bfloat16* __restrict__ qkvl,
    __nv_bfloat16* __restrict__ yh, __nv_bfloat16* __restrict__ yl)
{
    extern __shared__ char smem[];
    const uint32_t sb = smem_u32(smem);
    const int qt   = blockIdx.x;
    const int h    = blockIdx.y;
    const int b    = blockIdx.z;
    const int tid  = threadIdx.x;
    const int lane = tid & 31;
    const int warp = tid >> 5;

    const size_t rs = (size_t)3 * C_;
    const __nv_bfloat16* Qh = qkvh + ((size_t)(b * T_ + qt * 128)) * rs + h * D_;
    const __nv_bfloat16* Ql = qkvl + ((size_t)(b * T_ + qt * 128)) * rs + h * D_;
    const __nv_bfloat16* Kh = qkvh + ((size_t)b * T_) * rs + C_     + h * D_;
    const __nv_bfloat16* Kl = qkvl + ((size_t)b * T_) * rs + C_     + h * D_;
    const __nv_bfloat16* Vh = qkvh + ((size_t)b * T_) * rs + 2 * C_ + h * D_;
    const __nv_bfloat16* Vl = qkvl + ((size_t)b * T_) * rs + 2 * C_ + h * D_;

    // ---- Q tile loads ----
#pragma unroll
    for (int i = 0; i < 4; i++) {
        int lin = i * 256 + tid;
        int r = lin >> 3, c = lin & 7;
        uint32_t so = swz128((uint32_t)(r * 128 + c * 16));
        cp_async16(sb + AQ_H + so, Qh + (size_t)r * rs + c * 8);
        cp_async16(sb + AQ_L + so, Ql + (size_t)r * rs + c * 8);
    }
    CP_COMMIT();

    auto issue_blk = [&](int kb) {
        const uint32_t s0 = sb + A_STG + (kb % 3) * A_SSZ;
        const size_t g0 = (size_t)(kb * 64) * rs;
#pragma unroll
        for (int i = 0; i < 2; i++) {
            int lin = i * 256 + tid;
            int r = lin >> 3, c = lin & 7;
            uint32_t so = swz128((uint32_t)(r * 128 + c * 16));
            size_t go = g0 + (size_t)r * rs + c * 8;
            cp_async16(s0 + 0     + so, Kh + go);
            cp_async16(s0 + 8192  + so, Kl + go);
            cp_async16(s0 + 16384 + so, Vh + go);
            cp_async16(s0 + 24576 + so, Vl + go);
        }
        CP_COMMIT();
    };

    const int nb = 2 * (qt + 1);       // >= 2 always
    issue_blk(0);
    CP_WAIT(1);                        // Q done (blk0 may be in flight)
    __syncthreads();

    // ---- Q fragments (resident) ----
    const int a_r = lane & 15, a_k = (lane >> 4) * 8;
    uint32_t fQh[4][4], fQl[4][4];
#pragma unroll
    for (int ks = 0; ks < 4; ks++) {
        uint32_t bo = swz128((uint32_t)((warp * 16 + a_r) * 128 + (ks * 16 + a_k) * 2));
        LDSM_X4(fQh[ks][0], fQh[ks][1], fQh[ks][2], fQh[ks][3], sb + AQ_H + bo);
        LDSM_X4(fQl[ks][0], fQl[ks][1], fQl[ks][2], fQl[ks][3], sb + AQ_L + bo);
    }
    issue_blk(1);

    float oacc[8][4];
#pragma unroll
    for (int j = 0; j < 8; j++)
#pragma unroll
        for (int r = 0; r < 4; r++) oacc[j][r] = 0.f;
    float mrow[2] = {-1e30f, -1e30f};
    float lrow[2] = {0.f, 0.f};

    const int b_rr = lane & 7, b_g = lane >> 3;
    const int b_row = (b_g >> 1) * 8 + b_rr;
    const int b_k   = (b_g & 1) * 8;
    const int qg0 = qt * 128 + warp * 16 + (lane >> 2);

    uint32_t kfh[2][2][2], kfl[2][2][2];   // [buf][tile][reg]
    uint32_t vfh[2][2][2], vfl[2][2][2];

    for (int kb = 0; kb < nb; kb++) {
        if (kb + 1 < nb) CP_WAIT(1); else CP_WAIT(0);
        __syncthreads();               // stage kb published
        if (kb + 2 < nb) issue_blk(kb + 2);

        const uint32_t sK = sb + A_STG + (kb % 3) * A_SSZ;
        const uint32_t sV = sK + 16384;

        // ---- S = Q K^T (bf16x3), frag-pipelined ----
        float sacc[8][4];
#pragma unroll
        for (int j = 0; j < 8; j++)
#pragma unroll
            for (int r = 0; r < 4; r++) sacc[j][r] = 0.f;

        A_LOAD_KFRAG(0, 0, 0);
#pragma unroll
        for (int it = 0; it < 16; it++) {
            const int ks = it >> 2, p = it & 3;
            if (it < 15) A_LOAD_KFRAG((it + 1) & 1, (it + 1) >> 2, (it + 1) & 3);
            const int bf = it & 1;
            MMA16816(sacc[2*p],   fQh[ks], kfh[bf][0]);
            MMA16816(sacc[2*p+1], fQh[ks], kfh[bf][1]);
            MMA16816(sacc[2*p],   fQh[ks], kfl[bf][0]);
            MMA16816(sacc[2*p+1], fQh[ks], kfl[bf][1]);
            MMA16816(sacc[2*p],   fQl[ks], kfh[bf][0]);
            MMA16816(sacc[2*p+1], fQl[ks], kfh[bf][1]);
        }

        // prefetch first V frags; latency hides under softmax
        A_LOAD_VFRAG(0, 0, 0);

        // ---- scale + causal mask ----
#pragma unroll
        for (int j = 0; j < 8; j++)
#pragma unroll
            for (int r = 0; r < 4; r++) sacc[j][r] *= 0.125f;
        if (kb >= 2 * qt) {
            const int kbase = kb * 64 + (lane & 3) * 2;
#pragma unroll
            for (int j = 0; j < 8; j++) {
#pragma unroll
                for (int cc = 0; cc < 2; cc++) {
                    int kg = kbase + j * 8 + cc;
                    if (kg > qg0)     sacc[j][cc]     = -1e30f;
                    if (kg > qg0 + 8) sacc[j][2 + cc] = -1e30f;
                }
            }
        }

        // ---- online softmax ----
        float m0 = mrow[0], m1 = mrow[1];
#pragma unroll
        for (int j = 0; j < 8; j++) {
            m0 = fmaxf(m0, fmaxf(sacc[j][0], sacc[j][1]));
            m1 = fmaxf(m1, fmaxf(sacc[j][2], sacc[j][3]));
        }
        m0 = fmaxf(m0, __shfl_xor_sync(0xffffffffu, m0, 1));
        m0 = fmaxf(m0, __shfl_xor_sync(0xffffffffu, m0, 2));
        m1 = fmaxf(m1, __shfl_xor_sync(0xffffffffu, m1, 1));
        m1 = fmaxf(m1, __shfl_xor_sync(0xffffffffu, m1, 2));
        const float f0 = __expf(mrow[0] - m0), f1 = __expf(mrow[1] - m1);
        mrow[0] = m0; mrow[1] = m1;
        lrow[0] *= f0; lrow[1] *= f1;
#pragma unroll
        for (int j = 0; j < 8; j++) {
            oacc[j][0] *= f0; oacc[j][1] *= f0;
            oacc[j][2] *= f1; oacc[j][3] *= f1;
        }

        uint32_t ah[4][4], al[4][4];
#pragma unroll
        for (int j = 0; j < 8; j++) {
            float p0 = __expf(sacc[j][0] - m0);
            float p1 = __expf(sacc[j][1] - m0);
            float p2 = __expf(sacc[j][2] - m1);
            float p3 = __expf(sacc[j][3] - m1);
            lrow[0] += p0 + p1;
            lrow[1] += p2 + p3;
            uint32_t ph01 = pack_bf16x2(p0, p1);
            uint32_t ph23 = pack_bf16x2(p2, p3);
            uint32_t pl01 = pack_bf16x2(p0 - bf16lo_f(ph01), p1 - bf16hi_f(ph01));
            uint32_t pl23 = pack_bf16x2(p2 - bf16lo_f(ph23), p3 - bf16hi_f(ph23));
            const int ks = j >> 1, sl = (j & 1) * 2;
            ah[ks][sl]     = ph01;  ah[ks][sl + 1] = ph23;
            al[ks][sl]     = pl01;  al[ks][sl + 1] = pl23;
        }

        // ---- O += P V (bf16x3), frag-pipelined ----
#pragma unroll
        for (int it = 0; it < 16; it++) {
            const int ks = it >> 2, p = it & 3;
            if (it < 15) A_LOAD_VFRAG((it + 1) & 1, (it + 1) >> 2, (it + 1) & 3);
            const int bf = it & 1;
            MMA16816(oacc[2*p],   ah[ks], vfh[bf][0]);
            MMA16816(oacc[2*p+1], ah[ks], vfh[bf][1]);
            MMA16816(oacc[2*p],   ah[ks], vfl[bf][0]);
            MMA16816(oacc[2*p+1], ah[ks], vfl[bf][1]);
            MMA16816(oacc[2*p],   al[ks], vfh[bf][0]);
            MMA16816(oacc[2*p+1], al[ks], vfh[bf][1]);
        }
        // no trailing barrier (3-stage ring)
    }

    // ---- finalize ----
    lrow[0] += __shfl_xor_sync(0xffffffffu, lrow[0], 1);
    lrow[0] += __shfl_xor_sync(0xffffffffu, lrow[0], 2);
    lrow[1] += __shfl_xor_sync(0xffffffffu, lrow[1], 1);
    lrow[1] += __shfl_xor_sync(0xffffffffu, lrow[1], 2);
    const float inv0 = 1.f / lrow[0], inv1 = 1.f / lrow[1];

    const int t0 = qt * 128 + warp * 16 + (lane >> 2);
    const size_t base0 = ((size_t)(b * T_ + t0)) * C_ + h * D_ + (lane & 3) * 2;
    const size_t base1 = base0 + 8 * (size_t)C_;
#pragma unroll
    for (int j = 0; j < 8; j++) {
        float y0 = oacc[j][0] * inv0, y1 = oacc[j][1] * inv0;
        float y2 = oacc[j][2] * inv1, y3 = oacc[j][3] * inv1;
        uint32_t h01 = pack_bf16x2(y0, y1);
        uint32_t l01 = pack_bf16x2(y0 - bf16lo_f(h01), y1 - bf16hi_f(h01));
        uint32_t h23 = pack_bf16x2(y2, y3);
        uint32_t l23 = pack_bf16x2(y2 - bf16lo_f(h23), y3 - bf16hi_f(h23));
        *(uint32_t*)(yh + base0 + j * 8) = h01;
        *(uint32_t*)(yl + base0 + j * 8) = l01;
        *(uint32_t*)(yh + base1 + j * 8) = h23;
        *(uint32_t*)(yl + base1 + j * 8) = l23;
    }
}

// ---------------------------------------------------------------------------
extern "C" void kernel_launch(void* const* d_in, const int* in_sizes, int n_in,
                              void* d_out, int out_size)
{
    const float* x     = (const float*)d_in[0];   // [B,T,C]
    const float* w_qkv = (const float*)d_in[1];   // [3C,C]
    const float* w_out = (const float*)d_in[2];   // [C,C]
    float* out = (float*)d_out;                   // [B,T,C]

    __nv_bfloat16 *qkvh, *qkvl, *xh, *xl, *yh, *yl, *wqh, *wql, *woh, *wol;
    cudaGetSymbolAddress((void**)&qkvh, g_qkvh); cudaGetSymbolAddress((void**)&qkvl, g_qkvl);
    cudaGetSymbolAddress((void**)&xh,  g_xh);  cudaGetSymbolAddress((void**)&xl,  g_xl);
    cudaGetSymbolAddress((void**)&yh,  g_yh);  cudaGetSymbolAddress((void**)&yl,  g_yl);
    cudaGetSymbolAddress((void**)&wqh, g_wqh); cudaGetSymbolAddress((void**)&wql, g_wql);
    cudaGetSymbolAddress((void**)&woh, g_woh); cudaGetSymbolAddress((void**)&wol, g_wol);

    cudaFuncSetAttribute(gemm_bf16x3<true>,  cudaFuncAttributeMaxDynamicSharedMemorySize, G_TOTAL);
    cudaFuncSetAttribute(gemm_bf16x3<false>, cudaFuncAttributeMaxDynamicSharedMemorySize, G_TOTAL);
    cudaFuncSetAttribute(attn_mma,           cudaFuncAttributeMaxDynamicSharedMemorySize, A_TOTAL);

    const int M = B_ * T_;                  // 8192
    const int n_x  = M * C_;
    const int n_wq = 3 * C_ * C_;
    const int n_wo = C_ * C_;

    split_kernel<<<(n_x / 4 + 255) / 256, 256>>>(x, xh, xl, n_x / 4);
    split_kernel<<<(n_wq / 4 + 255) / 256, 256>>>(w_qkv, wqh, wql, n_wq / 4);
    split_kernel<<<(n_wo / 4 + 255) / 256, 256>>>(w_out, woh, wol, n_wo / 4);

    // 1) qkv = x @ w_qkv^T -> bf16 hi/lo directly
    {
        dim3 grid(3 * C_ / 64, M / 128);
        gemm_bf16x3<true><<<grid, 256, G_TOTAL>>>(xh, xl, wqh, wql,
                                                  nullptr, qkvh, qkvl, 3 * C_, C_);
    }
    // 2) causal attention (bf16 in, bf16 hi/lo out)
    {
        dim3 grid(T_ / 128, H_, B_);
        attn_mma<<<grid, 256, A_TOTAL>>>(qkvh, qkvl, yh, yl);
    }
    // 3) out = y @ w_out^T -> fp32
    {
        dim3 grid(C_ / 64, M / 128);
        gemm_bf16x3<false><<<grid, 256, G_TOTAL>>>(yh, yl, woh, wol,
                                                   out, nullptr, nullptr, C_, C_);
    }
}